// round 14
// baseline (speedup 1.0000x reference)
#include <cuda_runtime.h>
#include <cstdint>
#include <math.h>

#define BATCH    2048
#define U        128
#define NLAYERS  8
#define NSTEPS   4            // contraction ~10x/sweep; residual ~1e-6 rel at 4
#define DT_A     0.1f
#define INVC     (1.0f/11.0f)
#define TANHK    10.0f
#define NCHUNKS  (NSTEPS * NLAYERS * 6 + 2)   // 194

typedef unsigned long long ull;

__device__ float g_Mt [NLAYERS * U * U];
__device__ float g_Nt [NLAYERS * U * U];      // pre-negated -(a/c) M W
__device__ float g_Mb [NLAYERS * U];
__device__ float g_WT [U * U];

__device__ __forceinline__ float4 ld4(const float* p) { return *(const float4*)p; }
__device__ __forceinline__ void   st4(float* p, float4 v) { *(float4*)p = v; }
#define FC(v,t) (((const float*)&(v))[t])

__device__ __forceinline__ ull pk2(float x, float y) {
    ull r; asm("mov.b64 %0, {%1,%2};" : "=l"(r) : "f"(x), "f"(y)); return r;
}
__device__ __forceinline__ ull splat(float x) { return pk2(x, x); }
__device__ __forceinline__ ull fma2(ull a, ull b, ull c) {
    ull d; asm("fma.rn.f32x2 %0, %1, %2, %3;" : "=l"(d) : "l"(a), "l"(b), "l"(c)); return d;
}
__device__ __forceinline__ void unpk2(ull v, float& lo, float& hi) {
    asm("mov.b64 {%0,%1}, %2;" : "=f"(lo), "=f"(hi) : "l"(v));
}
__device__ __forceinline__ uint32_t s2u(const void* p) {
    uint32_t a;
    asm("{ .reg .u64 t; cvta.to.shared.u64 t, %1; cvt.u32.u64 %0, t; }" : "=r"(a) : "l"(p));
    return a;
}
__device__ __forceinline__ void mbar_init(uint32_t m, uint32_t cnt) {
    asm volatile("mbarrier.init.shared.b64 [%0], %1;" :: "r"(m), "r"(cnt) : "memory");
}
__device__ __forceinline__ void mbar_expect(uint32_t m, uint32_t tx) {
    asm volatile("mbarrier.arrive.expect_tx.shared.b64 _, [%0], %1;" :: "r"(m), "r"(tx) : "memory");
}
__device__ __forceinline__ void mbar_arrive(uint32_t m) {
    asm volatile("mbarrier.arrive.release.cta.shared.b64 _, [%0];" :: "r"(m) : "memory");
}
__device__ __forceinline__ void bulk_g2s(uint32_t dst, const void* src, uint32_t bytes, uint32_t m) {
    asm volatile("cp.async.bulk.shared::cluster.global.mbarrier::complete_tx::bytes [%0], [%1], %2, [%3];"
                 :: "r"(dst), "l"(src), "r"(bytes), "r"(m) : "memory");
}
__device__ __forceinline__ void mbar_wait(uint32_t m, uint32_t phase) {
    uint32_t done;
    do {
        asm volatile("{\n\t.reg .pred p;\n\t"
                     "mbarrier.try_wait.parity.acquire.cta.shared::cta.b64 p, [%1], %2, 0x989680;\n\t"
                     "selp.b32 %0, 1, 0, p;\n\t}"
                     : "=r"(done) : "r"(m), "r"(phase) : "memory");
    } while (!done);
}
__device__ __forceinline__ int swz(int col) { return ((col >> 1) & 3) << 2; }

// ---------------- k_pre: prep only, 16 CTAs (layer x j-half), 512 thr ----------------
#define WS_S 132
#define ES   132
#define MS   68
#define PREP_SMEM ((128*WS_S + 128*ES + 128*MS) * 4)

__global__ __launch_bounds__(512) void k_pre(const float* __restrict__ wblocks,
                                             const float* __restrict__ bblocks)
{
    extern __shared__ float sm[];
    float* Wsh = sm;                  // [128][132]
    float* E   = sm + 128 * WS_S;     // [128][132]
    float* Mh  = E + 128 * ES;        // [128][68]
    const int tid = threadIdx.x;
    const int cid = blockIdx.x;
    const int l  = cid >> 1;
    const int h  = cid & 1;
    const int j0 = h * 64;
    const float* Wg = wblocks + l * U * U;

    for (int idx = tid; idx < U * U; idx += 512)
        Wsh[(idx >> 7) * WS_S + (idx & 127)] = Wg[idx];
    __syncthreads();

    // E = kscl * W W^T (full; 512 tiles of 4x8)
    const float kscl = (DT_A * DT_A) * INVC;
    {
        const int ti = tid >> 4, tj = tid & 15;
        float acc[4][8];
#pragma unroll
        for (int r = 0; r < 4; r++)
#pragma unroll
            for (int j = 0; j < 8; j++) acc[r][j] = 0.f;
        for (int k4 = 0; k4 < 32; k4++) {
            float4 wi[4], wj[8];
#pragma unroll
            for (int r = 0; r < 4; r++) wi[r] = ld4(&Wsh[(ti*4 + r) * WS_S + k4*4]);
#pragma unroll
            for (int j = 0; j < 8; j++) wj[j] = ld4(&Wsh[(tj*8 + j) * WS_S + k4*4]);
#pragma unroll
            for (int r = 0; r < 4; r++)
#pragma unroll
                for (int j = 0; j < 8; j++) {
                    acc[r][j] += wi[r].x * wj[j].x + wi[r].y * wj[j].y
                               + wi[r].z * wj[j].z + wi[r].w * wj[j].w;
                }
        }
#pragma unroll
        for (int r = 0; r < 4; r++)
#pragma unroll
            for (int j = 0; j < 8; j++)
                E[(ti*4 + r) * ES + tj*8 + j] = kscl * acc[r][j];
    }
    __syncthreads();

    // M-half = I - E + E^2 (cols j0..j0+63)
    {
        const int ti = tid >> 4, tj = tid & 15;
        float acc[4][4];
#pragma unroll
        for (int r = 0; r < 4; r++)
#pragma unroll
            for (int cjj = 0; cjj < 4; cjj++) acc[r][cjj] = 0.f;
        for (int k4 = 0; k4 < 32; k4++) {
            float4 ei[4], ej[4];
#pragma unroll
            for (int r = 0; r < 4; r++)   ei[r] = ld4(&E[(ti*4 + r) * ES + k4*4]);
#pragma unroll
            for (int cjj = 0; cjj < 4; cjj++) ej[cjj] = ld4(&E[(j0 + tj*4 + cjj) * ES + k4*4]);
#pragma unroll
            for (int r = 0; r < 4; r++)
#pragma unroll
                for (int cjj = 0; cjj < 4; cjj++) {
                    acc[r][cjj] += ei[r].x * ej[cjj].x + ei[r].y * ej[cjj].y
                                 + ei[r].z * ej[cjj].z + ei[r].w * ej[cjj].w;
                }
        }
#pragma unroll
        for (int r = 0; r < 4; r++)
#pragma unroll
            for (int cjj = 0; cjj < 4; cjj++) {
                const int i = ti*4 + r, j = j0 + tj*4 + cjj;
                Mh[i * MS + tj*4 + cjj] =
                    (i == j ? 1.f : 0.f) - E[i * ES + j] + acc[r][cjj];
            }
    }
    __syncthreads();

    for (int idx = tid; idx < 128 * 64; idx += 512) {
        const int k = idx >> 6, jh = idx & 63;
        g_Mt[l * 16384 + k * 128 + j0 + jh] = Mh[k * MS + jh];
    }
    if (tid < 64) {
        float s = 0.f;
        for (int m = 0; m < U; m++)
            s += Mh[m * MS + tid] * bblocks[l * U + m];
        g_Mb[l * U + j0 + tid] = DT_A * s;
    }
    {
        const float ac = -DT_A * INVC;
        const int tk = tid >> 4, tj = tid & 15;
        float acc[4][4];
#pragma unroll
        for (int r = 0; r < 4; r++)
#pragma unroll
            for (int cjj = 0; cjj < 4; cjj++) acc[r][cjj] = 0.f;
#pragma unroll 2
        for (int m = 0; m < U; m++) {
            const float4 wv = ld4(&Wsh[m * WS_S + tk*4]);
            const float4 mv = ld4(&Mh[m * MS + tj*4]);
#pragma unroll
            for (int r = 0; r < 4; r++)
#pragma unroll
                for (int cjj = 0; cjj < 4; cjj++)
                    acc[r][cjj] += FC(wv, r) * FC(mv, cjj);
        }
#pragma unroll
        for (int r = 0; r < 4; r++)
#pragma unroll
            for (int cjj = 0; cjj < 4; cjj++)
                g_Nt[l * 16384 + (tk*4 + r) * 128 + j0 + tj*4 + cjj] = ac * acc[r][cjj];
    }
    if (l == NLAYERS - 1 && h == 0) {
        for (int idx = tid; idx < U * U; idx += 512) {
            const int i = idx >> 7, j = idx & 127;
            g_WT[i * U + j] = Wsh[j * WS_S + i];
        }
    }
}

// ---------------- k_sweep (input projection fused into prologue) ----------------
#define SW_FLOATS 57512
#define SW_BYTES  (SW_FLOATS * 4)

__device__ __forceinline__ void prefetch_chunk(int c, uint32_t wbB, uint32_t mbar0,
                                               const float* __restrict__ wblocks)
{
    if (c >= NCHUNKS) return;
    const uint32_t dst = wbB + (uint32_t)(c & 1) * 32768u;
    const uint32_t mb  = mbar0 + (uint32_t)(c & 1) * 8u;
    mbar_expect(mb, 32768u);
    if (c >= NCHUNKS - 2) {
        bulk_g2s(dst, g_WT + (c - (NCHUNKS - 2)) * 8192, 32768u, mb);
    } else {
        const int step = c / 6;
        const int l = step & 7;
        const int r = c - step * 6;
        if (r < 4) {
            bulk_g2s(dst,          g_Mt + l * 16384 + r * 4096, 16384u, mb);
            bulk_g2s(dst + 16384u, g_Nt + l * 16384 + r * 4096, 16384u, mb);
        } else {
            bulk_g2s(dst, wblocks + l * 16384 + (r - 4) * 8192, 32768u, mb);
        }
    }
}

__global__ __launch_bounds__(512, 1) void k_sweep(const float* __restrict__ x,
                                                  const float* __restrict__ win,
                                                  const float* __restrict__ bin,
                                                  const float* __restrict__ wblocks,
                                                  const float* __restrict__ bblocks,
                                                  const float* __restrict__ wout,
                                                  const float* __restrict__ bout,
                                                  float* __restrict__ out)
{
    extern __shared__ float sm[];
    float* zinT = sm;
    float* zls  = sm + 4096;
    float* qT   = sm + 36864;
    float* wb   = sm + 38912;
    float* bb   = sm + 55296;
    float* Mbs  = sm + 56320;
    float* lg   = sm + 57344;

    const uint32_t smem0 = s2u(sm);
    const uint32_t mbar0 = smem0 + 57504u * 4u;
    const uint32_t mbarE = smem0 + 57508u * 4u;
    const uint32_t wbB   = smem0 + 38912u * 4u;

    const int tid  = threadIdx.x;
    const int wid  = tid >> 5;
    const int lane = tid & 31;
    const int ks   = wid >> 3;
    const int rh   = (wid >> 2) & 1;
    const int cq   = wid & 3;
    const int rg   = lane >> 4;
    const int cp   = lane & 15;
    const int col2  = cq * 32 + cp * 2;
    const int rbase = rh * 8 + rg * 4;
    const int rb_s  = rbase ^ ((cp & 3) << 2);
    const int ks16  = ks * 16;
    const int row0  = blockIdx.x * 16;

    // ---- prologue: barriers + first weight prefetches + fused input proj ----
    if (tid == 0) {
        mbar_init(mbar0, 1);
        mbar_init(mbar0 + 8, 1);
        mbar_init(mbarE, 16);
        mbar_init(mbarE + 8, 16);
        asm volatile("fence.mbarrier_init.release.cluster;" ::: "memory");
    }
    __syncthreads();
    if (tid == 0) { prefetch_chunk(0, wbB, mbar0, wblocks); prefetch_chunk(1, wbB, mbar0, wblocks); }

    // stage x tile [16][784] into zls region (dead until z init)
    {
        const float4* xs4 = (const float4*)(x + row0 * 784);
        float4* d4 = (float4*)zls;
        for (int idx = tid; idx < 3136; idx += 512) d4[idx] = xs4[idx];
    }
    for (int idx = tid; idx < 1024; idx += 512) bb[idx] = bblocks[idx];
    for (int idx = tid; idx < 1024; idx += 512) Mbs[idx] = g_Mb[idx];
    __syncthreads();

    // projection: thread = (col 0..127) x (4-row group 0..3)
    float pr[4];
    {
        const int pcol = tid & 127;
        const int prg  = tid >> 7;
        const float* wr = win + pcol * 784;
        const float* xr = zls + prg * 4 * 784;
        float a0 = 0.f, a1 = 0.f, a2 = 0.f, a3 = 0.f;
        for (int k4 = 0; k4 < 196; k4++) {
            const float4 wv = ld4(wr + k4 * 4);
            const float4 x0 = ld4(xr + k4 * 4);
            const float4 x1 = ld4(xr + 784 + k4 * 4);
            const float4 x2 = ld4(xr + 1568 + k4 * 4);
            const float4 x3 = ld4(xr + 2352 + k4 * 4);
            a0 += x0.x*wv.x + x0.y*wv.y + x0.z*wv.z + x0.w*wv.w;
            a1 += x1.x*wv.x + x1.y*wv.y + x1.z*wv.z + x1.w*wv.w;
            a2 += x2.x*wv.x + x2.y*wv.y + x2.z*wv.z + x2.w*wv.w;
            a3 += x3.x*wv.x + x3.y*wv.y + x3.z*wv.z + x3.w*wv.w;
        }
        const float b = bin[pcol];
        pr[0] = a0 + b; pr[1] = a1 + b; pr[2] = a2 + b; pr[3] = a3 + b;
    }
    __syncthreads();   // all staging reads of zls done
    {
        const int pcol = tid & 127;
        const int prg  = tid >> 7;
#pragma unroll
        for (int r = 0; r < 4; r++) {
            const int row = prg * 4 + r;
            const int so = row ^ swz(pcol);
            zinT[pcol * 16 + so]        = pr[r];
            zinT[2048 + pcol * 16 + so] = tanhf(pr[r]);
        }
    }
    __syncthreads();
    for (int idx = tid; idx < 32768; idx += 512) zls[idx] = zinT[idx & 4095];
#pragma unroll
    for (int s = 0; s < 2; s++) {
        const int ii = tid + s * 512;
        const int base = (ii >> 3) * 16 + (ii & 7) * 2;
        const float2 u2 = *(const float2*)&zinT[base];
        const float2 v2 = *(const float2*)&zinT[2048 + base];
        float2 q2;
        q2.x = TANHK * tanhf(u2.x) + v2.x;
        q2.y = TANHK * tanhf(u2.y) + v2.y;
        *(float2*)&qT[base] = q2;
    }
    __syncthreads();

    int c = 0;
    for (int it = 0; it < NSTEPS; it++) {
        for (int l = 0; l < NLAYERS; l++) {
            const float* cuT = l ? (zls + (l - 1) * 4096) : zinT;
            float* uTl = zls + l * 4096;
            float* vTl = uTl + 2048;

            // ---- u = M*carry + Mb + Ntneg*q (k-split; ring-synced) ----
            ull A0, A1, A2, A3;
            if (ks == 0) {
                const ull mb2 = *(const ull*)&Mbs[l * 128 + col2];
                A0 = mb2; A1 = mb2; A2 = mb2; A3 = mb2;
            } else {
                A0 = A1 = A2 = A3 = 0;
            }
            for (int kc = 0; kc < 4; kc++) {
                mbar_wait(mbar0 + (uint32_t)(c & 1) * 8u, (c >> 1) & 1);
                const float* Mt = wb + (c & 1) * 8192;
                const float* Nt = Mt + 4096;
#pragma unroll
                for (int kk4 = 0; kk4 < 4; kk4++) {
                    const int kb = ks16 + kk4 * 4;
                    const int kg = kc * 32 + kb;
                    const int oA = rbase ^ (((kg >> 1) & 3) << 2);
                    const int oB = rbase ^ ((((kg >> 1) + 1) & 3) << 2);
#pragma unroll
                    for (int t = 0; t < 4; t++) {
                        const ull mw = *(const ull*)&Mt[(kb + t) * 128 + col2];
                        const ull nw = *(const ull*)&Nt[(kb + t) * 128 + col2];
                        const int ao = (kg + t) * 16 + (t < 2 ? oA : oB);
                        const float4 cu = ld4(&cuT[ao]);
                        const float4 qq = ld4(&qT[ao]);
                        A0 = fma2(splat(cu.x), mw, A0);
                        A1 = fma2(splat(cu.y), mw, A1);
                        A2 = fma2(splat(cu.z), mw, A2);
                        A3 = fma2(splat(cu.w), mw, A3);
                        A0 = fma2(splat(qq.x), nw, A0);
                        A1 = fma2(splat(qq.y), nw, A1);
                        A2 = fma2(splat(qq.z), nw, A2);
                        A3 = fma2(splat(qq.w), nw, A3);
                    }
                }
                if (kc == 3 && ks == 1) {
                    float l0,h0,l1,h1,l2,h2,l3,h3;
                    unpk2(A0,l0,h0); unpk2(A1,l1,h1); unpk2(A2,l2,h2); unpk2(A3,l3,h3);
                    st4(&uTl[col2 * 16 + rb_s],       make_float4(l0,l1,l2,l3));
                    st4(&uTl[(col2 + 1) * 16 + rb_s], make_float4(h0,h1,h2,h3));
                }
                if (lane == 0) mbar_arrive(mbarE + (uint32_t)(c & 1) * 8u);
                if (wid == 0 && lane == 0 && c + 2 < NCHUNKS) {
                    mbar_wait(mbarE + (uint32_t)(c & 1) * 8u, (c >> 1) & 1);
                    prefetch_chunk(c + 2, wbB, mbar0, wblocks);
                }
                c++;
            }
            __syncthreads();
            if (ks == 0) {
                const float4 p0 = ld4(&uTl[col2 * 16 + rb_s]);
                const float4 p1 = ld4(&uTl[(col2 + 1) * 16 + rb_s]);
                float l0,h0,l1,h1,l2,h2,l3,h3;
                unpk2(A0,l0,h0); unpk2(A1,l1,h1); unpk2(A2,l2,h2); unpk2(A3,l3,h3);
                st4(&uTl[col2 * 16 + rb_s],
                    make_float4(l0+p0.x, l1+p0.y, l2+p0.z, l3+p0.w));
                st4(&uTl[(col2 + 1) * 16 + rb_s],
                    make_float4(h0+p1.x, h1+p1.y, h2+p1.z, h3+p1.w));
            }
            __syncthreads();

            // ---- v = (q + 0.1 * u W)/11 (j-split; ring-synced) ----
            ull V0 = 0, V1 = 0, V2 = 0, V3 = 0;
            for (int jc = 0; jc < 2; jc++) {
                mbar_wait(mbar0 + (uint32_t)(c & 1) * 8u, (c >> 1) & 1);
                const float* Ws = wb + (c & 1) * 8192;
#pragma unroll
                for (int jj4 = 0; jj4 < 8; jj4++) {
                    const int jb = ks * 32 + jj4 * 4;
                    const int jg = jc * 64 + jb;
                    const int oA = rbase ^ (((jg >> 1) & 3) << 2);
                    const int oB = rbase ^ ((((jg >> 1) + 1) & 3) << 2);
#pragma unroll
                    for (int t = 0; t < 4; t++) {
                        const ull w2 = *(const ull*)&Ws[(jb + t) * 128 + col2];
                        const int ao = (jg + t) * 16 + (t < 2 ? oA : oB);
                        const float4 u4 = ld4(&uTl[ao]);
                        V0 = fma2(splat(u4.x), w2, V0);
                        V1 = fma2(splat(u4.y), w2, V1);
                        V2 = fma2(splat(u4.z), w2, V2);
                        V3 = fma2(splat(u4.w), w2, V3);
                    }
                }
                if (jc == 1 && ks == 1) {
                    float l0,h0,l1,h1,l2,h2,l3,h3;
                    unpk2(V0,l0,h0); unpk2(V1,l1,h1); unpk2(V2,l2,h2); unpk2(V3,l3,h3);
                    st4(&vTl[col2 * 16 + rb_s],       make_float4(l0,l1,l2,l3));
                    st4(&vTl[(col2 + 1) * 16 + rb_s], make_float4(h0,h1,h2,h3));
                }
                if (lane == 0) mbar_arrive(mbarE + (uint32_t)(c & 1) * 8u);
                if (wid == 0 && lane == 0 && c + 2 < NCHUNKS) {
                    mbar_wait(mbarE + (uint32_t)(c & 1) * 8u, (c >> 1) & 1);
                    prefetch_chunk(c + 2, wbB, mbar0, wblocks);
                }
                c++;
            }
            __syncthreads();
            if (ks == 0) {
                const float4 p0 = ld4(&vTl[col2 * 16 + rb_s]);
                const float4 p1 = ld4(&vTl[(col2 + 1) * 16 + rb_s]);
                const float4 q0 = ld4(&qT[col2 * 16 + rb_s]);
                const float4 q1 = ld4(&qT[(col2 + 1) * 16 + rb_s]);
                float l0,h0,l1,h1,l2,h2,l3,h3;
                unpk2(V0,l0,h0); unpk2(V1,l1,h1); unpk2(V2,l2,h2); unpk2(V3,l3,h3);
                const float4 vv0 = make_float4(
                    (q0.x + DT_A * (l0 + p0.x)) * INVC,
                    (q0.y + DT_A * (l1 + p0.y)) * INVC,
                    (q0.z + DT_A * (l2 + p0.z)) * INVC,
                    (q0.w + DT_A * (l3 + p0.w)) * INVC);
                const float4 vv1 = make_float4(
                    (q1.x + DT_A * (h0 + p1.x)) * INVC,
                    (q1.y + DT_A * (h1 + p1.y)) * INVC,
                    (q1.z + DT_A * (h2 + p1.z)) * INVC,
                    (q1.w + DT_A * (h3 + p1.w)) * INVC);
                st4(&vTl[col2 * 16 + rb_s],       vv0);
                st4(&vTl[(col2 + 1) * 16 + rb_s], vv1);

                if (!(it == NSTEPS - 1 && l == NLAYERS - 1)) {
                    const float* uN = (l < NLAYERS - 1) ? (zls + (l + 1) * 4096) : zls;
                    const float4 un0 = ld4(&uN[col2 * 16 + rb_s]);
                    const float4 un1 = ld4(&uN[(col2 + 1) * 16 + rb_s]);
                    float4 cv0, cv1;
                    if (l < NLAYERS - 1) { cv0 = vv0; cv1 = vv1; }
                    else {
                        cv0 = ld4(&zinT[2048 + col2 * 16 + rb_s]);
                        cv1 = ld4(&zinT[2048 + (col2 + 1) * 16 + rb_s]);
                    }
                    float4 nq0, nq1;
                    nq0.x = TANHK * tanhf(un0.x) + cv0.x;
                    nq0.y = TANHK * tanhf(un0.y) + cv0.y;
                    nq0.z = TANHK * tanhf(un0.z) + cv0.z;
                    nq0.w = TANHK * tanhf(un0.w) + cv0.w;
                    nq1.x = TANHK * tanhf(un1.x) + cv1.x;
                    nq1.y = TANHK * tanhf(un1.y) + cv1.y;
                    nq1.z = TANHK * tanhf(un1.z) + cv1.z;
                    nq1.w = TANHK * tanhf(un1.w) + cv1.w;
                    st4(&qT[col2 * 16 + rb_s],       nq0);
                    st4(&qT[(col2 + 1) * 16 + rb_s], nq1);
                }
            }
            __syncthreads();
        }
    }

    // ---- final block -> qT row-major ----
    {
        ull A0 = 0, A1 = 0, A2 = 0, A3 = 0;
        const float* vT7 = zls + 7 * 4096 + 2048;
        float* scr = zls;
        for (int ic = 0; ic < 2; ic++) {
            mbar_wait(mbar0 + (uint32_t)(c & 1) * 8u, (c >> 1) & 1);
            const float* Ws = wb + (c & 1) * 8192;
#pragma unroll
            for (int ii4 = 0; ii4 < 8; ii4++) {
                const int ib = ks * 32 + ii4 * 4;
                const int ig = ic * 64 + ib;
                const int oA = rbase ^ (((ig >> 1) & 3) << 2);
                const int oB = rbase ^ ((((ig >> 1) + 1) & 3) << 2);
#pragma unroll
                for (int t = 0; t < 4; t++) {
                    const ull w2 = *(const ull*)&Ws[(ib + t) * 128 + col2];
                    const int ao = (ig + t) * 16 + (t < 2 ? oA : oB);
                    const float4 v4 = ld4(&vT7[ao]);
                    A0 = fma2(splat(v4.x), w2, A0);
                    A1 = fma2(splat(v4.y), w2, A1);
                    A2 = fma2(splat(v4.z), w2, A2);
                    A3 = fma2(splat(v4.w), w2, A3);
                }
            }
            if (ic == 1 && ks == 1) {
                float l0,h0,l1,h1,l2,h2,l3,h3;
                unpk2(A0,l0,h0); unpk2(A1,l1,h1); unpk2(A2,l2,h2); unpk2(A3,l3,h3);
                st4(&scr[col2 * 16 + rb_s],       make_float4(l0,l1,l2,l3));
                st4(&scr[(col2 + 1) * 16 + rb_s], make_float4(h0,h1,h2,h3));
            }
            if (lane == 0) mbar_arrive(mbarE + (uint32_t)(c & 1) * 8u);
            c++;
        }
        __syncthreads();
        if (ks == 0) {
            const float4 p0 = ld4(&scr[col2 * 16 + rb_s]);
            const float4 p1 = ld4(&scr[(col2 + 1) * 16 + rb_s]);
            const float b0 = DT_A * bb[7 * 128 + col2];
            const float b1 = DT_A * bb[7 * 128 + col2 + 1];
            float l0,h0,l1,h1,l2,h2,l3,h3;
            unpk2(A0,l0,h0); unpk2(A1,l1,h1); unpk2(A2,l2,h2); unpk2(A3,l3,h3);
            const float sl[4] = {l0+p0.x, l1+p0.y, l2+p0.z, l3+p0.w};
            const float sh[4] = {h0+p1.x, h1+p1.y, h2+p1.z, h3+p1.w};
#pragma unroll
            for (int i = 0; i < 4; i++) {
                const int r = rbase + i;
                const float r0 = zinT[col2 * 16 + rb_s + i]       + b0 - DT_A * sl[i];
                const float r1 = zinT[(col2 + 1) * 16 + rb_s + i] + b1 - DT_A * sh[i];
                *(ull*)&qT[r * 128 + col2] = pk2(r0, r1);
            }
        }
        __syncthreads();
    }

    // ---- logits + softmax ----
    for (int t = tid; t < 160; t += 512) {
        const int r = t / 10, o = t % 10;
        const float* ur = qT + r * 128;
        const float* wr = wout + o * 128;
        float a = bout[o];
#pragma unroll 4
        for (int k = 0; k < U; k++) a += ur[k] * wr[k];
        lg[t] = a;
    }
    __syncthreads();
    if (tid < 16) {
        float mx = -1e30f;
#pragma unroll
        for (int o = 0; o < 10; o++) mx = fmaxf(mx, lg[tid * 10 + o]);
        float e[10], s = 0.f;
#pragma unroll
        for (int o = 0; o < 10; o++) { e[o] = expf(lg[tid * 10 + o] - mx); s += e[o]; }
        const float inv = 1.0f / s;
#pragma unroll
        for (int o = 0; o < 10; o++) out[(row0 + tid) * 10 + o] = e[o] * inv;
    }
}

extern "C" void kernel_launch(void* const* d_in, const int* in_sizes, int n_in,
                              void* d_out, int out_size)
{
    const float* x     = (const float*)d_in[0];
    const float* w_in  = (const float*)d_in[1];
    const float* b_in  = (const float*)d_in[2];
    const float* w_blk = (const float*)d_in[3];
    const float* b_blk = (const float*)d_in[4];
    const float* w_out = (const float*)d_in[5];
    const float* b_out = (const float*)d_in[6];
    float* out = (float*)d_out;

    cudaFuncSetAttribute(k_pre,   cudaFuncAttributeMaxDynamicSharedMemorySize, PREP_SMEM);
    cudaFuncSetAttribute(k_sweep, cudaFuncAttributeMaxDynamicSharedMemorySize, SW_BYTES);

    k_pre  <<<16, 512, PREP_SMEM>>>(w_blk, b_blk);
    k_sweep<<<128, 512, SW_BYTES>>>(x, w_in, b_in, w_blk, b_blk, w_out, b_out, out);
}

// round 15
// speedup vs baseline: 1.8759x; 1.8759x over previous
#include <cuda_runtime.h>
#include <cstdint>
#include <math.h>

#define BATCH    2048
#define U        128
#define NLAYERS  8
#define NSTEPS   4            // measured R13: rel_err 1.19e-6 at 4 sweeps
#define DT_A     0.1f
#define INVC     (1.0f/11.0f)
#define TANHK    10.0f
#define NCHUNKS  (NSTEPS * NLAYERS * 6 + 2)   // 194

typedef unsigned long long ull;

__device__ float g_zin[BATCH * 256];
__device__ float g_Mt [NLAYERS * U * U];
__device__ float g_Nt [NLAYERS * U * U];      // pre-negated -(a/c) M W
__device__ float g_Mb [NLAYERS * U];
__device__ float g_WT [U * U];

__device__ __forceinline__ float4 ld4(const float* p) { return *(const float4*)p; }
__device__ __forceinline__ float2 ld2(const float* p) { return *(const float2*)p; }
__device__ __forceinline__ void   st4(float* p, float4 v) { *(float4*)p = v; }
#define FC(v,t) (((const float*)&(v))[t])

__device__ __forceinline__ ull pk2(float x, float y) {
    ull r; asm("mov.b64 %0, {%1,%2};" : "=l"(r) : "f"(x), "f"(y)); return r;
}
__device__ __forceinline__ ull splat(float x) { return pk2(x, x); }
__device__ __forceinline__ ull fma2(ull a, ull b, ull c) {
    ull d; asm("fma.rn.f32x2 %0, %1, %2, %3;" : "=l"(d) : "l"(a), "l"(b), "l"(c)); return d;
}
__device__ __forceinline__ void unpk2(ull v, float& lo, float& hi) {
    asm("mov.b64 {%0,%1}, %2;" : "=f"(lo), "=f"(hi) : "l"(v));
}
__device__ __forceinline__ uint32_t s2u(const void* p) {
    uint32_t a;
    asm("{ .reg .u64 t; cvta.to.shared.u64 t, %1; cvt.u32.u64 %0, t; }" : "=r"(a) : "l"(p));
    return a;
}
__device__ __forceinline__ void mbar_init(uint32_t m, uint32_t cnt) {
    asm volatile("mbarrier.init.shared.b64 [%0], %1;" :: "r"(m), "r"(cnt) : "memory");
}
__device__ __forceinline__ void mbar_expect(uint32_t m, uint32_t tx) {
    asm volatile("mbarrier.arrive.expect_tx.shared.b64 _, [%0], %1;" :: "r"(m), "r"(tx) : "memory");
}
__device__ __forceinline__ void mbar_arrive(uint32_t m) {
    asm volatile("mbarrier.arrive.release.cta.shared.b64 _, [%0];" :: "r"(m) : "memory");
}
__device__ __forceinline__ void bulk_g2s(uint32_t dst, const void* src, uint32_t bytes, uint32_t m) {
    asm volatile("cp.async.bulk.shared::cluster.global.mbarrier::complete_tx::bytes [%0], [%1], %2, [%3];"
                 :: "r"(dst), "l"(src), "r"(bytes), "r"(m) : "memory");
}
__device__ __forceinline__ void mbar_wait(uint32_t m, uint32_t phase) {
    uint32_t done;
    do {
        asm volatile("{\n\t.reg .pred p;\n\t"
                     "mbarrier.try_wait.parity.acquire.cta.shared::cta.b64 p, [%1], %2, 0x989680;\n\t"
                     "selp.b32 %0, 1, 0, p;\n\t}"
                     : "=r"(done) : "r"(m), "r"(phase) : "memory");
    } while (!done);
}
__device__ __forceinline__ int swz(int col) { return ((col >> 1) & 3) << 2; }

// ---------------- k_pre: prep halves (CTAs 0..15) + input proj (16..143), 512 thr ----
#define WS_S 132
#define ES   132
#define MS   68
#define PREP_SMEM ((128*WS_S + 128*ES + 128*MS) * 4)

__device__ void prep_body(float* sm, const float* __restrict__ wblocks,
                          const float* __restrict__ bblocks, int cid)
{
    float* Wsh = sm;                  // [128][132]
    float* E   = sm + 128 * WS_S;     // [128][132]
    float* Mh  = E + 128 * ES;        // [128][68]
    const int tid = threadIdx.x;
    const int l  = cid >> 1;
    const int h  = cid & 1;
    const int j0 = h * 64;
    const float* Wg = wblocks + l * U * U;

    for (int idx = tid; idx < U * U; idx += 512)
        Wsh[(idx >> 7) * WS_S + (idx & 127)] = Wg[idx];
    __syncthreads();

    // E = kscl * W W^T (full; 512 tiles of 4x8)
    const float kscl = (DT_A * DT_A) * INVC;
    {
        const int ti = tid >> 4, tj = tid & 15;
        float acc[4][8];
#pragma unroll
        for (int r = 0; r < 4; r++)
#pragma unroll
            for (int j = 0; j < 8; j++) acc[r][j] = 0.f;
        for (int k4 = 0; k4 < 32; k4++) {
            float4 wi[4], wj[8];
#pragma unroll
            for (int r = 0; r < 4; r++) wi[r] = ld4(&Wsh[(ti*4 + r) * WS_S + k4*4]);
#pragma unroll
            for (int j = 0; j < 8; j++) wj[j] = ld4(&Wsh[(tj*8 + j) * WS_S + k4*4]);
#pragma unroll
            for (int r = 0; r < 4; r++)
#pragma unroll
                for (int j = 0; j < 8; j++) {
                    acc[r][j] += wi[r].x * wj[j].x + wi[r].y * wj[j].y
                               + wi[r].z * wj[j].z + wi[r].w * wj[j].w;
                }
        }
#pragma unroll
        for (int r = 0; r < 4; r++)
#pragma unroll
            for (int j = 0; j < 8; j++)
                E[(ti*4 + r) * ES + tj*8 + j] = kscl * acc[r][j];
    }
    __syncthreads();

    // M-half = I - E + E^2 (cols j0..j0+63)
    {
        const int ti = tid >> 4, tj = tid & 15;
        float acc[4][4];
#pragma unroll
        for (int r = 0; r < 4; r++)
#pragma unroll
            for (int cjj = 0; cjj < 4; cjj++) acc[r][cjj] = 0.f;
        for (int k4 = 0; k4 < 32; k4++) {
            float4 ei[4], ej[4];
#pragma unroll
            for (int r = 0; r < 4; r++)   ei[r] = ld4(&E[(ti*4 + r) * ES + k4*4]);
#pragma unroll
            for (int cjj = 0; cjj < 4; cjj++) ej[cjj] = ld4(&E[(j0 + tj*4 + cjj) * ES + k4*4]);
#pragma unroll
            for (int r = 0; r < 4; r++)
#pragma unroll
                for (int cjj = 0; cjj < 4; cjj++) {
                    acc[r][cjj] += ei[r].x * ej[cjj].x + ei[r].y * ej[cjj].y
                                 + ei[r].z * ej[cjj].z + ei[r].w * ej[cjj].w;
                }
        }
#pragma unroll
        for (int r = 0; r < 4; r++)
#pragma unroll
            for (int cjj = 0; cjj < 4; cjj++) {
                const int i = ti*4 + r, j = j0 + tj*4 + cjj;
                Mh[i * MS + tj*4 + cjj] =
                    (i == j ? 1.f : 0.f) - E[i * ES + j] + acc[r][cjj];
            }
    }
    __syncthreads();

    for (int idx = tid; idx < 128 * 64; idx += 512) {
        const int k = idx >> 6, jh = idx & 63;
        g_Mt[l * 16384 + k * 128 + j0 + jh] = Mh[k * MS + jh];
    }
    if (tid < 64) {
        float s = 0.f;
        for (int m = 0; m < U; m++)
            s += Mh[m * MS + tid] * bblocks[l * U + m];
        g_Mb[l * U + j0 + tid] = DT_A * s;
    }
    {
        const float ac = -DT_A * INVC;
        const int tk = tid >> 4, tj = tid & 15;
        float acc[4][4];
#pragma unroll
        for (int r = 0; r < 4; r++)
#pragma unroll
            for (int cjj = 0; cjj < 4; cjj++) acc[r][cjj] = 0.f;
#pragma unroll 2
        for (int m = 0; m < U; m++) {
            const float4 wv = ld4(&Wsh[m * WS_S + tk*4]);
            const float4 mv = ld4(&Mh[m * MS + tj*4]);
#pragma unroll
            for (int r = 0; r < 4; r++)
#pragma unroll
                for (int cjj = 0; cjj < 4; cjj++)
                    acc[r][cjj] += FC(wv, r) * FC(mv, cjj);
        }
#pragma unroll
        for (int r = 0; r < 4; r++)
#pragma unroll
            for (int cjj = 0; cjj < 4; cjj++)
                g_Nt[l * 16384 + (tk*4 + r) * 128 + j0 + tj*4 + cjj] = ac * acc[r][cjj];
    }
    if (l == NLAYERS - 1 && h == 0) {
        for (int idx = tid; idx < U * U; idx += 512) {
            const int i = idx >> 7, j = idx & 127;
            g_WT[i * U + j] = Wsh[j * WS_S + i];
        }
    }
}

__device__ void input_body(float* sm, const float* __restrict__ x,
                           const float* __restrict__ win,
                           const float* __restrict__ bin, int bid)
{
    float* ws = sm;            // [16][132]
    float* xs = sm + 16 * 132; // [16][20]
    const int tid = threadIdx.x;
    const int row0 = bid * 16;
    const int rg = tid >> 6;   // 0..7, 2 rows each
    const int cg = tid & 63;   // 2 cols each

    float2 acc[2];
    acc[0] = make_float2(0.f, 0.f);
    acc[1] = make_float2(0.f, 0.f);

    for (int kc = 0; kc < 49; kc++) {
        const int k0 = kc * 16;
        __syncthreads();
        {   // coalesced: ws[kk][n] = win[n][k0+kk]; 512 threads x 1 float4
            const int n = tid & 127, h = tid >> 7;    // h 0..3
            const float* wr = win + n * 784 + k0 + h * 4;
            float4 a = ld4(wr);
            ws[(h*4+0)*132 + n] = a.x; ws[(h*4+1)*132 + n] = a.y;
            ws[(h*4+2)*132 + n] = a.z; ws[(h*4+3)*132 + n] = a.w;
        }
        if (tid < 256) {
            const int r = tid >> 4, kk = tid & 15;
            xs[kk * 20 + r] = x[(row0 + r) * 784 + k0 + kk];
        }
        __syncthreads();
#pragma unroll
        for (int kk = 0; kk < 16; kk++) {
            const float2 wv = ld2(&ws[kk * 132 + cg * 2]);
            const float xv0 = xs[kk * 20 + rg * 2];
            const float xv1 = xs[kk * 20 + rg * 2 + 1];
            acc[0].x += xv0 * wv.x; acc[0].y += xv0 * wv.y;
            acc[1].x += xv1 * wv.x; acc[1].y += xv1 * wv.y;
        }
    }

    const float2 b2 = ld2(bin + cg * 2);
    acc[0].x += b2.x; acc[0].y += b2.y;
    acc[1].x += b2.x; acc[1].y += b2.y;
    float* base = g_zin + bid * 4096;
#pragma unroll
    for (int cc = 0; cc < 2; cc++) {
        const int col = cg * 2 + cc;
        const int so = (rg * 2) ^ swz(col);
        const float a0 = cc ? acc[0].y : acc[0].x;
        const float a1 = cc ? acc[1].y : acc[1].x;
        *(ull*)&base[col * 16 + so]        = pk2(a0, a1);
        *(ull*)&base[2048 + col * 16 + so] = pk2(tanhf(a0), tanhf(a1));
    }
}

__global__ __launch_bounds__(512) void k_pre(const float* __restrict__ x,
                                             const float* __restrict__ win,
                                             const float* __restrict__ bin,
                                             const float* __restrict__ wblocks,
                                             const float* __restrict__ bblocks)
{
    extern __shared__ float sm[];
    if (blockIdx.x < 16) prep_body(sm, wblocks, bblocks, blockIdx.x);
    else                 input_body(sm, x, win, bin, blockIdx.x - 16);
}

// ---------------- k_sweep ----------------
#define SW_FLOATS 57512
#define SW_BYTES  (SW_FLOATS * 4)

__device__ __forceinline__ void prefetch_chunk(int c, uint32_t wbB, uint32_t mbar0,
                                               const float* __restrict__ wblocks)
{
    if (c >= NCHUNKS) return;
    const uint32_t dst = wbB + (uint32_t)(c & 1) * 32768u;
    const uint32_t mb  = mbar0 + (uint32_t)(c & 1) * 8u;
    mbar_expect(mb, 32768u);
    if (c >= NCHUNKS - 2) {
        bulk_g2s(dst, g_WT + (c - (NCHUNKS - 2)) * 8192, 32768u, mb);
    } else {
        const int step = c / 6;
        const int l = step & 7;
        const int r = c - step * 6;
        if (r < 4) {
            bulk_g2s(dst,          g_Mt + l * 16384 + r * 4096, 16384u, mb);
            bulk_g2s(dst + 16384u, g_Nt + l * 16384 + r * 4096, 16384u, mb);
        } else {
            bulk_g2s(dst, wblocks + l * 16384 + (r - 4) * 8192, 32768u, mb);
        }
    }
}

__global__ __launch_bounds__(512, 1) void k_sweep(const float* __restrict__ wblocks,
                                                  const float* __restrict__ bblocks,
                                                  const float* __restrict__ wout,
                                                  const float* __restrict__ bout,
                                                  float* __restrict__ out)
{
    extern __shared__ float sm[];
    float* zinT = sm;
    float* zls  = sm + 4096;
    float* qT   = sm + 36864;
    float* wb   = sm + 38912;
    float* bb   = sm + 55296;
    float* Mbs  = sm + 56320;
    float* lg   = sm + 57344;

    const uint32_t smem0 = s2u(sm);
    const uint32_t mbar0 = smem0 + 57504u * 4u;
    const uint32_t mbarE = smem0 + 57508u * 4u;
    const uint32_t wbB   = smem0 + 38912u * 4u;

    const int tid  = threadIdx.x;
    const int wid  = tid >> 5;
    const int lane = tid & 31;
    const int ks   = wid >> 3;
    const int rh   = (wid >> 2) & 1;
    const int cq   = wid & 3;
    const int rg   = lane >> 4;
    const int cp   = lane & 15;
    const int col2  = cq * 32 + cp * 2;
    const int rbase = rh * 8 + rg * 4;
    const int rb_s  = rbase ^ ((cp & 3) << 2);
    const int ks16  = ks * 16;
    const int row0  = blockIdx.x * 16;

    for (int idx = tid; idx < 4096; idx += 512) zinT[idx] = g_zin[row0 * 256 + idx];
    for (int idx = tid; idx < 1024; idx += 512) bb[idx] = bblocks[idx];
    for (int idx = tid; idx < 1024; idx += 512) Mbs[idx] = g_Mb[idx];
    if (tid == 0) {
        mbar_init(mbar0, 1);
        mbar_init(mbar0 + 8, 1);
        mbar_init(mbarE, 16);
        mbar_init(mbarE + 8, 16);
        asm volatile("fence.mbarrier_init.release.cluster;" ::: "memory");
    }
    __syncthreads();
    for (int idx = tid; idx < 32768; idx += 512) zls[idx] = zinT[idx & 4095];
#pragma unroll
    for (int s = 0; s < 2; s++) {
        const int ii = tid + s * 512;
        const int base = (ii >> 3) * 16 + (ii & 7) * 2;
        const float2 u2 = *(const float2*)&zinT[base];
        const float2 v2 = *(const float2*)&zinT[2048 + base];
        float2 q2;
        q2.x = TANHK * tanhf(u2.x) + v2.x;
        q2.y = TANHK * tanhf(u2.y) + v2.y;
        *(float2*)&qT[base] = q2;
    }
    if (tid == 0) { prefetch_chunk(0, wbB, mbar0, wblocks); prefetch_chunk(1, wbB, mbar0, wblocks); }
    __syncthreads();

    int c = 0;
    for (int it = 0; it < NSTEPS; it++) {
        for (int l = 0; l < NLAYERS; l++) {
            const float* cuT = l ? (zls + (l - 1) * 4096) : zinT;
            float* uTl = zls + l * 4096;
            float* vTl = uTl + 2048;

            // ---- u = M*carry + Mb + Ntneg*q (k-split; ring-synced) ----
            ull A0, A1, A2, A3;
            if (ks == 0) {
                const ull mb2 = *(const ull*)&Mbs[l * 128 + col2];
                A0 = mb2; A1 = mb2; A2 = mb2; A3 = mb2;
            } else {
                A0 = A1 = A2 = A3 = 0;
            }
            for (int kc = 0; kc < 4; kc++) {
                mbar_wait(mbar0 + (uint32_t)(c & 1) * 8u, (c >> 1) & 1);
                const float* Mt = wb + (c & 1) * 8192;
                const float* Nt = Mt + 4096;
#pragma unroll
                for (int kk4 = 0; kk4 < 4; kk4++) {
                    const int kb = ks16 + kk4 * 4;
                    const int kg = kc * 32 + kb;
                    const int oA = rbase ^ (((kg >> 1) & 3) << 2);
                    const int oB = rbase ^ ((((kg >> 1) + 1) & 3) << 2);
#pragma unroll
                    for (int t = 0; t < 4; t++) {
                        const ull mw = *(const ull*)&Mt[(kb + t) * 128 + col2];
                        const ull nw = *(const ull*)&Nt[(kb + t) * 128 + col2];
                        const int ao = (kg + t) * 16 + (t < 2 ? oA : oB);
                        const float4 cu = ld4(&cuT[ao]);
                        const float4 qq = ld4(&qT[ao]);
                        A0 = fma2(splat(cu.x), mw, A0);
                        A1 = fma2(splat(cu.y), mw, A1);
                        A2 = fma2(splat(cu.z), mw, A2);
                        A3 = fma2(splat(cu.w), mw, A3);
                        A0 = fma2(splat(qq.x), nw, A0);
                        A1 = fma2(splat(qq.y), nw, A1);
                        A2 = fma2(splat(qq.z), nw, A2);
                        A3 = fma2(splat(qq.w), nw, A3);
                    }
                }
                if (kc == 3 && ks == 1) {
                    float l0,h0,l1,h1,l2,h2,l3,h3;
                    unpk2(A0,l0,h0); unpk2(A1,l1,h1); unpk2(A2,l2,h2); unpk2(A3,l3,h3);
                    st4(&uTl[col2 * 16 + rb_s],       make_float4(l0,l1,l2,l3));
                    st4(&uTl[(col2 + 1) * 16 + rb_s], make_float4(h0,h1,h2,h3));
                }
                if (lane == 0) mbar_arrive(mbarE + (uint32_t)(c & 1) * 8u);
                if (wid == 0 && lane == 0 && c + 2 < NCHUNKS) {
                    mbar_wait(mbarE + (uint32_t)(c & 1) * 8u, (c >> 1) & 1);
                    prefetch_chunk(c + 2, wbB, mbar0, wblocks);
                }
                c++;
            }
            __syncthreads();
            if (ks == 0) {
                const float4 p0 = ld4(&uTl[col2 * 16 + rb_s]);
                const float4 p1 = ld4(&uTl[(col2 + 1) * 16 + rb_s]);
                float l0,h0,l1,h1,l2,h2,l3,h3;
                unpk2(A0,l0,h0); unpk2(A1,l1,h1); unpk2(A2,l2,h2); unpk2(A3,l3,h3);
                st4(&uTl[col2 * 16 + rb_s],
                    make_float4(l0+p0.x, l1+p0.y, l2+p0.z, l3+p0.w));
                st4(&uTl[(col2 + 1) * 16 + rb_s],
                    make_float4(h0+p1.x, h1+p1.y, h2+p1.z, h3+p1.w));
            }
            __syncthreads();

            // ---- v = (q + 0.1 * u W)/11 (j-split; ring-synced) ----
            ull V0 = 0, V1 = 0, V2 = 0, V3 = 0;
            for (int jc = 0; jc < 2; jc++) {
                mbar_wait(mbar0 + (uint32_t)(c & 1) * 8u, (c >> 1) & 1);
                const float* Ws = wb + (c & 1) * 8192;
#pragma unroll
                for (int jj4 = 0; jj4 < 8; jj4++) {
                    const int jb = ks * 32 + jj4 * 4;
                    const int jg = jc * 64 + jb;
                    const int oA = rbase ^ (((jg >> 1) & 3) << 2);
                    const int oB = rbase ^ ((((jg >> 1) + 1) & 3) << 2);
#pragma unroll
                    for (int t = 0; t < 4; t++) {
                        const ull w2 = *(const ull*)&Ws[(jb + t) * 128 + col2];
                        const int ao = (jg + t) * 16 + (t < 2 ? oA : oB);
                        const float4 u4 = ld4(&uTl[ao]);
                        V0 = fma2(splat(u4.x), w2, V0);
                        V1 = fma2(splat(u4.y), w2, V1);
                        V2 = fma2(splat(u4.z), w2, V2);
                        V3 = fma2(splat(u4.w), w2, V3);
                    }
                }
                if (jc == 1 && ks == 1) {
                    float l0,h0,l1,h1,l2,h2,l3,h3;
                    unpk2(V0,l0,h0); unpk2(V1,l1,h1); unpk2(V2,l2,h2); unpk2(V3,l3,h3);
                    st4(&vTl[col2 * 16 + rb_s],       make_float4(l0,l1,l2,l3));
                    st4(&vTl[(col2 + 1) * 16 + rb_s], make_float4(h0,h1,h2,h3));
                }
                if (lane == 0) mbar_arrive(mbarE + (uint32_t)(c & 1) * 8u);
                if (wid == 0 && lane == 0 && c + 2 < NCHUNKS) {
                    mbar_wait(mbarE + (uint32_t)(c & 1) * 8u, (c >> 1) & 1);
                    prefetch_chunk(c + 2, wbB, mbar0, wblocks);
                }
                c++;
            }
            __syncthreads();
            if (ks == 0) {
                const float4 p0 = ld4(&vTl[col2 * 16 + rb_s]);
                const float4 p1 = ld4(&vTl[(col2 + 1) * 16 + rb_s]);
                const float4 q0 = ld4(&qT[col2 * 16 + rb_s]);
                const float4 q1 = ld4(&qT[(col2 + 1) * 16 + rb_s]);
                float l0,h0,l1,h1,l2,h2,l3,h3;
                unpk2(V0,l0,h0); unpk2(V1,l1,h1); unpk2(V2,l2,h2); unpk2(V3,l3,h3);
                const float4 vv0 = make_float4(
                    (q0.x + DT_A * (l0 + p0.x)) * INVC,
                    (q0.y + DT_A * (l1 + p0.y)) * INVC,
                    (q0.z + DT_A * (l2 + p0.z)) * INVC,
                    (q0.w + DT_A * (l3 + p0.w)) * INVC);
                const float4 vv1 = make_float4(
                    (q1.x + DT_A * (h0 + p1.x)) * INVC,
                    (q1.y + DT_A * (h1 + p1.y)) * INVC,
                    (q1.z + DT_A * (h2 + p1.z)) * INVC,
                    (q1.w + DT_A * (h3 + p1.w)) * INVC);
                st4(&vTl[col2 * 16 + rb_s],       vv0);
                st4(&vTl[(col2 + 1) * 16 + rb_s], vv1);

                if (!(it == NSTEPS - 1 && l == NLAYERS - 1)) {
                    const float* uN = (l < NLAYERS - 1) ? (zls + (l + 1) * 4096) : zls;
                    const float4 un0 = ld4(&uN[col2 * 16 + rb_s]);
                    const float4 un1 = ld4(&uN[(col2 + 1) * 16 + rb_s]);
                    float4 cv0, cv1;
                    if (l < NLAYERS - 1) { cv0 = vv0; cv1 = vv1; }
                    else {
                        cv0 = ld4(&zinT[2048 + col2 * 16 + rb_s]);
                        cv1 = ld4(&zinT[2048 + (col2 + 1) * 16 + rb_s]);
                    }
                    float4 nq0, nq1;
                    nq0.x = TANHK * tanhf(un0.x) + cv0.x;
                    nq0.y = TANHK * tanhf(un0.y) + cv0.y;
                    nq0.z = TANHK * tanhf(un0.z) + cv0.z;
                    nq0.w = TANHK * tanhf(un0.w) + cv0.w;
                    nq1.x = TANHK * tanhf(un1.x) + cv1.x;
                    nq1.y = TANHK * tanhf(un1.y) + cv1.y;
                    nq1.z = TANHK * tanhf(un1.z) + cv1.z;
                    nq1.w = TANHK * tanhf(un1.w) + cv1.w;
                    st4(&qT[col2 * 16 + rb_s],       nq0);
                    st4(&qT[(col2 + 1) * 16 + rb_s], nq1);
                }
            }
            __syncthreads();
        }
    }

    // ---- final block -> qT row-major ----
    {
        ull A0 = 0, A1 = 0, A2 = 0, A3 = 0;
        const float* vT7 = zls + 7 * 4096 + 2048;
        float* scr = zls;
        for (int ic = 0; ic < 2; ic++) {
            mbar_wait(mbar0 + (uint32_t)(c & 1) * 8u, (c >> 1) & 1);
            const float* Ws = wb + (c & 1) * 8192;
#pragma unroll
            for (int ii4 = 0; ii4 < 8; ii4++) {
                const int ib = ks * 32 + ii4 * 4;
                const int ig = ic * 64 + ib;
                const int oA = rbase ^ (((ig >> 1) & 3) << 2);
                const int oB = rbase ^ ((((ig >> 1) + 1) & 3) << 2);
#pragma unroll
                for (int t = 0; t < 4; t++) {
                    const ull w2 = *(const ull*)&Ws[(ib + t) * 128 + col2];
                    const int ao = (ig + t) * 16 + (t < 2 ? oA : oB);
                    const float4 v4 = ld4(&vT7[ao]);
                    A0 = fma2(splat(v4.x), w2, A0);
                    A1 = fma2(splat(v4.y), w2, A1);
                    A2 = fma2(splat(v4.z), w2, A2);
                    A3 = fma2(splat(v4.w), w2, A3);
                }
            }
            if (ic == 1 && ks == 1) {
                float l0,h0,l1,h1,l2,h2,l3,h3;
                unpk2(A0,l0,h0); unpk2(A1,l1,h1); unpk2(A2,l2,h2); unpk2(A3,l3,h3);
                st4(&scr[col2 * 16 + rb_s],       make_float4(l0,l1,l2,l3));
                st4(&scr[(col2 + 1) * 16 + rb_s], make_float4(h0,h1,h2,h3));
            }
            if (lane == 0) mbar_arrive(mbarE + (uint32_t)(c & 1) * 8u);
            c++;
        }
        __syncthreads();
        if (ks == 0) {
            const float4 p0 = ld4(&scr[col2 * 16 + rb_s]);
            const float4 p1 = ld4(&scr[(col2 + 1) * 16 + rb_s]);
            const float b0 = DT_A * bb[7 * 128 + col2];
            const float b1 = DT_A * bb[7 * 128 + col2 + 1];
            float l0,h0,l1,h1,l2,h2,l3,h3;
            unpk2(A0,l0,h0); unpk2(A1,l1,h1); unpk2(A2,l2,h2); unpk2(A3,l3,h3);
            const float sl[4] = {l0+p0.x, l1+p0.y, l2+p0.z, l3+p0.w};
            const float sh[4] = {h0+p1.x, h1+p1.y, h2+p1.z, h3+p1.w};
#pragma unroll
            for (int i = 0; i < 4; i++) {
                const int r = rbase + i;
                const float r0 = zinT[col2 * 16 + rb_s + i]       + b0 - DT_A * sl[i];
                const float r1 = zinT[(col2 + 1) * 16 + rb_s + i] + b1 - DT_A * sh[i];
                *(ull*)&qT[r * 128 + col2] = pk2(r0, r1);
            }
        }
        __syncthreads();
    }

    // ---- logits + softmax ----
    for (int t = tid; t < 160; t += 512) {
        const int r = t / 10, o = t % 10;
        const float* ur = qT + r * 128;
        const float* wr = wout + o * 128;
        float a = bout[o];
#pragma unroll 4
        for (int k = 0; k < U; k++) a += ur[k] * wr[k];
        lg[t] = a;
    }
    __syncthreads();
    if (tid < 16) {
        float mx = -1e30f;
#pragma unroll
        for (int o = 0; o < 10; o++) mx = fmaxf(mx, lg[tid * 10 + o]);
        float e[10], s = 0.f;
#pragma unroll
        for (int o = 0; o < 10; o++) { e[o] = expf(lg[tid * 10 + o] - mx); s += e[o]; }
        const float inv = 1.0f / s;
#pragma unroll
        for (int o = 0; o < 10; o++) out[(row0 + tid) * 10 + o] = e[o] * inv;
    }
}

extern "C" void kernel_launch(void* const* d_in, const int* in_sizes, int n_in,
                              void* d_out, int out_size)
{
    const float* x     = (const float*)d_in[0];
    const float* w_in  = (const float*)d_in[1];
    const float* b_in  = (const float*)d_in[2];
    const float* w_blk = (const float*)d_in[3];
    const float* b_blk = (const float*)d_in[4];
    const float* w_out = (const float*)d_in[5];
    const float* b_out = (const float*)d_in[6];
    float* out = (float*)d_out;

    cudaFuncSetAttribute(k_pre,   cudaFuncAttributeMaxDynamicSharedMemorySize, PREP_SMEM);
    cudaFuncSetAttribute(k_sweep, cudaFuncAttributeMaxDynamicSharedMemorySize, SW_BYTES);

    k_pre  <<<144, 512, PREP_SMEM>>>(x, w_in, b_in, w_blk, b_blk);
    k_sweep<<<128, 512, SW_BYTES>>>(w_blk, b_blk, w_out, b_out, out);
}

// round 16
// speedup vs baseline: 2.2088x; 1.1774x over previous
#include <cuda_runtime.h>
#include <cstdint>
#include <math.h>

#define BATCH    2048
#define U        128
#define NLAYERS  8
#define NSTEPS   4            // measured R13/R14: rel_err 1.19e-6 at 4 sweeps
#define DT_A     0.1f
#define INVC     (1.0f/11.0f)
#define TANHK    10.0f
#define NCHUNKS  (NSTEPS * NLAYERS * 6 + 2)   // 194

typedef unsigned long long ull;

__device__ float g_zin[BATCH * 256];
__device__ float g_Mt [NLAYERS * U * U];
__device__ float g_Nt [NLAYERS * U * U];      // pre-negated -(a/c) M W
__device__ float g_Mb [NLAYERS * U];
__device__ float g_WT [U * U];

__device__ __forceinline__ float4 ld4(const float* p) { return *(const float4*)p; }
__device__ __forceinline__ float2 ld2(const float* p) { return *(const float2*)p; }
__device__ __forceinline__ void   st4(float* p, float4 v) { *(float4*)p = v; }
#define FC(v,t) (((const float*)&(v))[t])

__device__ __forceinline__ ull pk2(float x, float y) {
    ull r; asm("mov.b64 %0, {%1,%2};" : "=l"(r) : "f"(x), "f"(y)); return r;
}
__device__ __forceinline__ ull splat(float x) { return pk2(x, x); }
__device__ __forceinline__ ull fma2(ull a, ull b, ull c) {
    ull d; asm("fma.rn.f32x2 %0, %1, %2, %3;" : "=l"(d) : "l"(a), "l"(b), "l"(c)); return d;
}
__device__ __forceinline__ void unpk2(ull v, float& lo, float& hi) {
    asm("mov.b64 {%0,%1}, %2;" : "=f"(lo), "=f"(hi) : "l"(v));
}
__device__ __forceinline__ uint32_t s2u(const void* p) {
    uint32_t a;
    asm("{ .reg .u64 t; cvta.to.shared.u64 t, %1; cvt.u32.u64 %0, t; }" : "=r"(a) : "l"(p));
    return a;
}
__device__ __forceinline__ void mbar_init(uint32_t m, uint32_t cnt) {
    asm volatile("mbarrier.init.shared.b64 [%0], %1;" :: "r"(m), "r"(cnt) : "memory");
}
__device__ __forceinline__ void mbar_expect(uint32_t m, uint32_t tx) {
    asm volatile("mbarrier.arrive.expect_tx.shared.b64 _, [%0], %1;" :: "r"(m), "r"(tx) : "memory");
}
__device__ __forceinline__ void mbar_arrive(uint32_t m) {
    asm volatile("mbarrier.arrive.release.cta.shared.b64 _, [%0];" :: "r"(m) : "memory");
}
__device__ __forceinline__ void bulk_g2s(uint32_t dst, const void* src, uint32_t bytes, uint32_t m) {
    asm volatile("cp.async.bulk.shared::cluster.global.mbarrier::complete_tx::bytes [%0], [%1], %2, [%3];"
                 :: "r"(dst), "l"(src), "r"(bytes), "r"(m) : "memory");
}
__device__ __forceinline__ void mbar_wait(uint32_t m, uint32_t phase) {
    uint32_t done;
    do {
        asm volatile("{\n\t.reg .pred p;\n\t"
                     "mbarrier.try_wait.parity.acquire.cta.shared::cta.b64 p, [%1], %2, 0x989680;\n\t"
                     "selp.b32 %0, 1, 0, p;\n\t}"
                     : "=r"(done) : "r"(m), "r"(phase) : "memory");
    } while (!done);
}
__device__ __forceinline__ int swz(int col) { return ((col >> 1) & 3) << 2; }

// ---------------- k_pre: prep halves (CTAs 0..15) + input proj (16..143), 512 thr ----
// prep v4: interleaved column tiling (cols = tj + 16*j) so lane-to-lane row
// stride is 1 row (132 floats == 4 banks) -> 2-way LDS conflicts instead of
// the 16-way (8-row stride == 0 mod 32 banks) of v3.
#define WS_S 132
#define ES   132
#define MS   68
#define PREP_SMEM ((128*WS_S + 128*ES + 128*MS) * 4)

__device__ void prep_body(float* sm, const float* __restrict__ wblocks,
                          const float* __restrict__ bblocks, int cid)
{
    float* Wsh = sm;                  // [128][132]
    float* E   = sm + 128 * WS_S;     // [128][132]
    float* Mh  = E + 128 * ES;        // [128][68]
    const int tid = threadIdx.x;
    const int l  = cid >> 1;
    const int h  = cid & 1;
    const int j0 = h * 64;
    const float* Wg = wblocks + l * U * U;

    for (int idx = tid; idx < U * U; idx += 512)
        Wsh[(idx >> 7) * WS_S + (idx & 127)] = Wg[idx];
    __syncthreads();

    // E = kscl * W W^T   (thread (ti,tj): rows ti*4+r, cols tj+16*j)
    const float kscl = (DT_A * DT_A) * INVC;
    {
        const int ti = tid >> 4, tj = tid & 15;
        float acc[4][8];
#pragma unroll
        for (int r = 0; r < 4; r++)
#pragma unroll
            for (int j = 0; j < 8; j++) acc[r][j] = 0.f;
        for (int k4 = 0; k4 < 32; k4++) {
            float4 wi[4], wj[8];
#pragma unroll
            for (int r = 0; r < 4; r++) wi[r] = ld4(&Wsh[(ti*4 + r) * WS_S + k4*4]);
#pragma unroll
            for (int j = 0; j < 8; j++) wj[j] = ld4(&Wsh[(tj + 16*j) * WS_S + k4*4]);
#pragma unroll
            for (int r = 0; r < 4; r++)
#pragma unroll
                for (int j = 0; j < 8; j++) {
                    acc[r][j] += wi[r].x * wj[j].x + wi[r].y * wj[j].y
                               + wi[r].z * wj[j].z + wi[r].w * wj[j].w;
                }
        }
#pragma unroll
        for (int r = 0; r < 4; r++)
#pragma unroll
            for (int j = 0; j < 8; j++)
                E[(ti*4 + r) * ES + tj + 16*j] = kscl * acc[r][j];
    }
    __syncthreads();

    // M-half = I - E + E^2 (cols j0 + tj + 16*cjj; E symmetric -> row dots)
    {
        const int ti = tid >> 4, tj = tid & 15;
        float acc[4][4];
#pragma unroll
        for (int r = 0; r < 4; r++)
#pragma unroll
            for (int cjj = 0; cjj < 4; cjj++) acc[r][cjj] = 0.f;
        for (int k4 = 0; k4 < 32; k4++) {
            float4 ei[4], ej[4];
#pragma unroll
            for (int r = 0; r < 4; r++)   ei[r] = ld4(&E[(ti*4 + r) * ES + k4*4]);
#pragma unroll
            for (int cjj = 0; cjj < 4; cjj++) ej[cjj] = ld4(&E[(j0 + tj + 16*cjj) * ES + k4*4]);
#pragma unroll
            for (int r = 0; r < 4; r++)
#pragma unroll
                for (int cjj = 0; cjj < 4; cjj++) {
                    acc[r][cjj] += ei[r].x * ej[cjj].x + ei[r].y * ej[cjj].y
                                 + ei[r].z * ej[cjj].z + ei[r].w * ej[cjj].w;
                }
        }
#pragma unroll
        for (int r = 0; r < 4; r++)
#pragma unroll
            for (int cjj = 0; cjj < 4; cjj++) {
                const int i = ti*4 + r;
                const int jc = tj + 16*cjj;          // 0..63 within half
                const int j = j0 + jc;
                Mh[i * MS + jc] =
                    (i == j ? 1.f : 0.f) - E[i * ES + j] + acc[r][cjj];
            }
    }
    __syncthreads();

    for (int idx = tid; idx < 128 * 64; idx += 512) {
        const int k = idx >> 6, jh = idx & 63;
        g_Mt[l * 16384 + k * 128 + j0 + jh] = Mh[k * MS + jh];
    }
    if (tid < 64) {
        float s = 0.f;
        for (int m = 0; m < U; m++)
            s += Mh[m * MS + tid] * bblocks[l * U + m];
        g_Mb[l * U + j0 + tid] = DT_A * s;
    }
    {
        const float ac = -DT_A * INVC;
        const int tk = tid >> 4, tj = tid & 15;
        float acc[4][4];
#pragma unroll
        for (int r = 0; r < 4; r++)
#pragma unroll
            for (int cjj = 0; cjj < 4; cjj++) acc[r][cjj] = 0.f;
#pragma unroll 2
        for (int m = 0; m < U; m++) {
            const float4 wv = ld4(&Wsh[m * WS_S + tk*4]);
            const float4 mv = ld4(&Mh[m * MS + tj*4]);
#pragma unroll
            for (int r = 0; r < 4; r++)
#pragma unroll
                for (int cjj = 0; cjj < 4; cjj++)
                    acc[r][cjj] += FC(wv, r) * FC(mv, cjj);
        }
#pragma unroll
        for (int r = 0; r < 4; r++)
#pragma unroll
            for (int cjj = 0; cjj < 4; cjj++)
                g_Nt[l * 16384 + (tk*4 + r) * 128 + j0 + tj*4 + cjj] = ac * acc[r][cjj];
    }
    if (l == NLAYERS - 1 && h == 0) {
        for (int idx = tid; idx < U * U; idx += 512) {
            const int i = idx >> 7, j = idx & 127;
            g_WT[i * U + j] = Wsh[j * WS_S + i];
        }
    }
}

__device__ void input_body(float* sm, const float* __restrict__ x,
                           const float* __restrict__ win,
                           const float* __restrict__ bin, int bid)
{
    float* ws = sm;            // [16][132]
    float* xs = sm + 16 * 132; // [16][20]
    const int tid = threadIdx.x;
    const int row0 = bid * 16;
    const int rg = tid >> 6;   // 0..7, 2 rows each
    const int cg = tid & 63;   // 2 cols each

    float2 acc[2];
    acc[0] = make_float2(0.f, 0.f);
    acc[1] = make_float2(0.f, 0.f);

    for (int kc = 0; kc < 49; kc++) {
        const int k0 = kc * 16;
        __syncthreads();
        {   // ws[kk][n] = win[n][k0+kk]; 512 threads x 1 float4
            const int n = tid & 127, h = tid >> 7;    // h 0..3
            const float* wr = win + n * 784 + k0 + h * 4;
            float4 a = ld4(wr);
            ws[(h*4+0)*132 + n] = a.x; ws[(h*4+1)*132 + n] = a.y;
            ws[(h*4+2)*132 + n] = a.z; ws[(h*4+3)*132 + n] = a.w;
        }
        if (tid < 256) {
            const int r = tid >> 4, kk = tid & 15;
            xs[kk * 20 + r] = x[(row0 + r) * 784 + k0 + kk];
        }
        __syncthreads();
#pragma unroll
        for (int kk = 0; kk < 16; kk++) {
            const float2 wv = ld2(&ws[kk * 132 + cg * 2]);
            const float xv0 = xs[kk * 20 + rg * 2];
            const float xv1 = xs[kk * 20 + rg * 2 + 1];
            acc[0].x += xv0 * wv.x; acc[0].y += xv0 * wv.y;
            acc[1].x += xv1 * wv.x; acc[1].y += xv1 * wv.y;
        }
    }

    const float2 b2 = ld2(bin + cg * 2);
    acc[0].x += b2.x; acc[0].y += b2.y;
    acc[1].x += b2.x; acc[1].y += b2.y;
    float* base = g_zin + bid * 4096;
#pragma unroll
    for (int cc = 0; cc < 2; cc++) {
        const int col = cg * 2 + cc;
        const int so = (rg * 2) ^ swz(col);
        const float a0 = cc ? acc[0].y : acc[0].x;
        const float a1 = cc ? acc[1].y : acc[1].x;
        *(ull*)&base[col * 16 + so]        = pk2(a0, a1);
        *(ull*)&base[2048 + col * 16 + so] = pk2(tanhf(a0), tanhf(a1));
    }
}

__global__ __launch_bounds__(512) void k_pre(const float* __restrict__ x,
                                             const float* __restrict__ win,
                                             const float* __restrict__ bin,
                                             const float* __restrict__ wblocks,
                                             const float* __restrict__ bblocks)
{
    extern __shared__ float sm[];
    if (blockIdx.x < 16) prep_body(sm, wblocks, bblocks, blockIdx.x);
    else                 input_body(sm, x, win, bin, blockIdx.x - 16);
}

// ---------------- k_sweep ----------------
#define SW_FLOATS 57512
#define SW_BYTES  (SW_FLOATS * 4)

__device__ __forceinline__ void prefetch_chunk(int c, uint32_t wbB, uint32_t mbar0,
                                               const float* __restrict__ wblocks)
{
    if (c >= NCHUNKS) return;
    const uint32_t dst = wbB + (uint32_t)(c & 1) * 32768u;
    const uint32_t mb  = mbar0 + (uint32_t)(c & 1) * 8u;
    mbar_expect(mb, 32768u);
    if (c >= NCHUNKS - 2) {
        bulk_g2s(dst, g_WT + (c - (NCHUNKS - 2)) * 8192, 32768u, mb);
    } else {
        const int step = c / 6;
        const int l = step & 7;
        const int r = c - step * 6;
        if (r < 4) {
            bulk_g2s(dst,          g_Mt + l * 16384 + r * 4096, 16384u, mb);
            bulk_g2s(dst + 16384u, g_Nt + l * 16384 + r * 4096, 16384u, mb);
        } else {
            bulk_g2s(dst, wblocks + l * 16384 + (r - 4) * 8192, 32768u, mb);
        }
    }
}

__global__ __launch_bounds__(512, 1) void k_sweep(const float* __restrict__ wblocks,
                                                  const float* __restrict__ bblocks,
                                                  const float* __restrict__ wout,
                                                  const float* __restrict__ bout,
                                                  float* __restrict__ out)
{
    extern __shared__ float sm[];
    float* zinT = sm;
    float* zls  = sm + 4096;
    float* qT   = sm + 36864;
    float* wb   = sm + 38912;
    float* bb   = sm + 55296;
    float* Mbs  = sm + 56320;
    float* lg   = sm + 57344;

    const uint32_t smem0 = s2u(sm);
    const uint32_t mbar0 = smem0 + 57504u * 4u;
    const uint32_t mbarE = smem0 + 57508u * 4u;
    const uint32_t wbB   = smem0 + 38912u * 4u;

    const int tid  = threadIdx.x;
    const int wid  = tid >> 5;
    const int lane = tid & 31;
    const int ks   = wid >> 3;
    const int rh   = (wid >> 2) & 1;
    const int cq   = wid & 3;
    const int rg   = lane >> 4;
    const int cp   = lane & 15;
    const int col2  = cq * 32 + cp * 2;
    const int rbase = rh * 8 + rg * 4;
    const int rb_s  = rbase ^ ((cp & 3) << 2);
    const int ks16  = ks * 16;
    const int row0  = blockIdx.x * 16;

    for (int idx = tid; idx < 4096; idx += 512) zinT[idx] = g_zin[row0 * 256 + idx];
    for (int idx = tid; idx < 1024; idx += 512) bb[idx] = bblocks[idx];
    for (int idx = tid; idx < 1024; idx += 512) Mbs[idx] = g_Mb[idx];
    if (tid == 0) {
        mbar_init(mbar0, 1);
        mbar_init(mbar0 + 8, 1);
        mbar_init(mbarE, 16);
        mbar_init(mbarE + 8, 16);
        asm volatile("fence.mbarrier_init.release.cluster;" ::: "memory");
    }
    __syncthreads();
    for (int idx = tid; idx < 32768; idx += 512) zls[idx] = zinT[idx & 4095];
#pragma unroll
    for (int s = 0; s < 2; s++) {
        const int ii = tid + s * 512;
        const int base = (ii >> 3) * 16 + (ii & 7) * 2;
        const float2 u2 = *(const float2*)&zinT[base];
        const float2 v2 = *(const float2*)&zinT[2048 + base];
        float2 q2;
        q2.x = TANHK * tanhf(u2.x) + v2.x;
        q2.y = TANHK * tanhf(u2.y) + v2.y;
        *(float2*)&qT[base] = q2;
    }
    if (tid == 0) { prefetch_chunk(0, wbB, mbar0, wblocks); prefetch_chunk(1, wbB, mbar0, wblocks); }
    __syncthreads();

    int c = 0;
    for (int it = 0; it < NSTEPS; it++) {
        for (int l = 0; l < NLAYERS; l++) {
            const float* cuT = l ? (zls + (l - 1) * 4096) : zinT;
            float* uTl = zls + l * 4096;
            float* vTl = uTl + 2048;

            // ---- u = M*carry + Mb + Ntneg*q (k-split; ring-synced) ----
            ull A0, A1, A2, A3;
            if (ks == 0) {
                const ull mb2 = *(const ull*)&Mbs[l * 128 + col2];
                A0 = mb2; A1 = mb2; A2 = mb2; A3 = mb2;
            } else {
                A0 = A1 = A2 = A3 = 0;
            }
            for (int kc = 0; kc < 4; kc++) {
                mbar_wait(mbar0 + (uint32_t)(c & 1) * 8u, (c >> 1) & 1);
                const float* Mt = wb + (c & 1) * 8192;
                const float* Nt = Mt + 4096;
#pragma unroll
                for (int kk4 = 0; kk4 < 4; kk4++) {
                    const int kb = ks16 + kk4 * 4;
                    const int kg = kc * 32 + kb;
                    const int oA = rbase ^ (((kg >> 1) & 3) << 2);
                    const int oB = rbase ^ ((((kg >> 1) + 1) & 3) << 2);
#pragma unroll
                    for (int t = 0; t < 4; t++) {
                        const ull mw = *(const ull*)&Mt[(kb + t) * 128 + col2];
                        const ull nw = *(const ull*)&Nt[(kb + t) * 128 + col2];
                        const int ao = (kg + t) * 16 + (t < 2 ? oA : oB);
                        const float4 cu = ld4(&cuT[ao]);
                        const float4 qq = ld4(&qT[ao]);
                        A0 = fma2(splat(cu.x), mw, A0);
                        A1 = fma2(splat(cu.y), mw, A1);
                        A2 = fma2(splat(cu.z), mw, A2);
                        A3 = fma2(splat(cu.w), mw, A3);
                        A0 = fma2(splat(qq.x), nw, A0);
                        A1 = fma2(splat(qq.y), nw, A1);
                        A2 = fma2(splat(qq.z), nw, A2);
                        A3 = fma2(splat(qq.w), nw, A3);
                    }
                }
                if (kc == 3 && ks == 1) {
                    float l0,h0,l1,h1,l2,h2,l3,h3;
                    unpk2(A0,l0,h0); unpk2(A1,l1,h1); unpk2(A2,l2,h2); unpk2(A3,l3,h3);
                    st4(&uTl[col2 * 16 + rb_s],       make_float4(l0,l1,l2,l3));
                    st4(&uTl[(col2 + 1) * 16 + rb_s], make_float4(h0,h1,h2,h3));
                }
                if (lane == 0) mbar_arrive(mbarE + (uint32_t)(c & 1) * 8u);
                if (wid == 0 && lane == 0 && c + 2 < NCHUNKS) {
                    mbar_wait(mbarE + (uint32_t)(c & 1) * 8u, (c >> 1) & 1);
                    prefetch_chunk(c + 2, wbB, mbar0, wblocks);
                }
                c++;
            }
            __syncthreads();
            if (ks == 0) {
                const float4 p0 = ld4(&uTl[col2 * 16 + rb_s]);
                const float4 p1 = ld4(&uTl[(col2 + 1) * 16 + rb_s]);
                float l0,h0,l1,h1,l2,h2,l3,h3;
                unpk2(A0,l0,h0); unpk2(A1,l1,h1); unpk2(A2,l2,h2); unpk2(A3,l3,h3);
                st4(&uTl[col2 * 16 + rb_s],
                    make_float4(l0+p0.x, l1+p0.y, l2+p0.z, l3+p0.w));
                st4(&uTl[(col2 + 1) * 16 + rb_s],
                    make_float4(h0+p1.x, h1+p1.y, h2+p1.z, h3+p1.w));
            }
            __syncthreads();

            // ---- v = (q + 0.1 * u W)/11 (j-split; ring-synced) ----
            ull V0 = 0, V1 = 0, V2 = 0, V3 = 0;
            for (int jc = 0; jc < 2; jc++) {
                mbar_wait(mbar0 + (uint32_t)(c & 1) * 8u, (c >> 1) & 1);
                const float* Ws = wb + (c & 1) * 8192;
#pragma unroll
                for (int jj4 = 0; jj4 < 8; jj4++) {
                    const int jb = ks * 32 + jj4 * 4;
                    const int jg = jc * 64 + jb;
                    const int oA = rbase ^ (((jg >> 1) & 3) << 2);
                    const int oB = rbase ^ ((((jg >> 1) + 1) & 3) << 2);
#pragma unroll
                    for (int t = 0; t < 4; t++) {
                        const ull w2 = *(const ull*)&Ws[(jb + t) * 128 + col2];
                        const int ao = (jg + t) * 16 + (t < 2 ? oA : oB);
                        const float4 u4 = ld4(&uTl[ao]);
                        V0 = fma2(splat(u4.x), w2, V0);
                        V1 = fma2(splat(u4.y), w2, V1);
                        V2 = fma2(splat(u4.z), w2, V2);
                        V3 = fma2(splat(u4.w), w2, V3);
                    }
                }
                if (jc == 1 && ks == 1) {
                    float l0,h0,l1,h1,l2,h2,l3,h3;
                    unpk2(V0,l0,h0); unpk2(V1,l1,h1); unpk2(V2,l2,h2); unpk2(V3,l3,h3);
                    st4(&vTl[col2 * 16 + rb_s],       make_float4(l0,l1,l2,l3));
                    st4(&vTl[(col2 + 1) * 16 + rb_s], make_float4(h0,h1,h2,h3));
                }
                if (lane == 0) mbar_arrive(mbarE + (uint32_t)(c & 1) * 8u);
                if (wid == 0 && lane == 0 && c + 2 < NCHUNKS) {
                    mbar_wait(mbarE + (uint32_t)(c & 1) * 8u, (c >> 1) & 1);
                    prefetch_chunk(c + 2, wbB, mbar0, wblocks);
                }
                c++;
            }
            __syncthreads();
            if (ks == 0) {
                const float4 p0 = ld4(&vTl[col2 * 16 + rb_s]);
                const float4 p1 = ld4(&vTl[(col2 + 1) * 16 + rb_s]);
                const float4 q0 = ld4(&qT[col2 * 16 + rb_s]);
                const float4 q1 = ld4(&qT[(col2 + 1) * 16 + rb_s]);
                float l0,h0,l1,h1,l2,h2,l3,h3;
                unpk2(V0,l0,h0); unpk2(V1,l1,h1); unpk2(V2,l2,h2); unpk2(V3,l3,h3);
                const float4 vv0 = make_float4(
                    (q0.x + DT_A * (l0 + p0.x)) * INVC,
                    (q0.y + DT_A * (l1 + p0.y)) * INVC,
                    (q0.z + DT_A * (l2 + p0.z)) * INVC,
                    (q0.w + DT_A * (l3 + p0.w)) * INVC);
                const float4 vv1 = make_float4(
                    (q1.x + DT_A * (h0 + p1.x)) * INVC,
                    (q1.y + DT_A * (h1 + p1.y)) * INVC,
                    (q1.z + DT_A * (h2 + p1.z)) * INVC,
                    (q1.w + DT_A * (h3 + p1.w)) * INVC);
                st4(&vTl[col2 * 16 + rb_s],       vv0);
                st4(&vTl[(col2 + 1) * 16 + rb_s], vv1);

                if (!(it == NSTEPS - 1 && l == NLAYERS - 1)) {
                    const float* uN = (l < NLAYERS - 1) ? (zls + (l + 1) * 4096) : zls;
                    const float4 un0 = ld4(&uN[col2 * 16 + rb_s]);
                    const float4 un1 = ld4(&uN[(col2 + 1) * 16 + rb_s]);
                    float4 cv0, cv1;
                    if (l < NLAYERS - 1) { cv0 = vv0; cv1 = vv1; }
                    else {
                        cv0 = ld4(&zinT[2048 + col2 * 16 + rb_s]);
                        cv1 = ld4(&zinT[2048 + (col2 + 1) * 16 + rb_s]);
                    }
                    float4 nq0, nq1;
                    nq0.x = TANHK * tanhf(un0.x) + cv0.x;
                    nq0.y = TANHK * tanhf(un0.y) + cv0.y;
                    nq0.z = TANHK * tanhf(un0.z) + cv0.z;
                    nq0.w = TANHK * tanhf(un0.w) + cv0.w;
                    nq1.x = TANHK * tanhf(un1.x) + cv1.x;
                    nq1.y = TANHK * tanhf(un1.y) + cv1.y;
                    nq1.z = TANHK * tanhf(un1.z) + cv1.z;
                    nq1.w = TANHK * tanhf(un1.w) + cv1.w;
                    st4(&qT[col2 * 16 + rb_s],       nq0);
                    st4(&qT[(col2 + 1) * 16 + rb_s], nq1);
                }
            }
            __syncthreads();
        }
    }

    // ---- final block -> qT row-major ----
    {
        ull A0 = 0, A1 = 0, A2 = 0, A3 = 0;
        const float* vT7 = zls + 7 * 4096 + 2048;
        float* scr = zls;
        for (int ic = 0; ic < 2; ic++) {
            mbar_wait(mbar0 + (uint32_t)(c & 1) * 8u, (c >> 1) & 1);
            const float* Ws = wb + (c & 1) * 8192;
#pragma unroll
            for (int ii4 = 0; ii4 < 8; ii4++) {
                const int ib = ks * 32 + ii4 * 4;
                const int ig = ic * 64 + ib;
                const int oA = rbase ^ (((ig >> 1) & 3) << 2);
                const int oB = rbase ^ ((((ig >> 1) + 1) & 3) << 2);
#pragma unroll
                for (int t = 0; t < 4; t++) {
                    const ull w2 = *(const ull*)&Ws[(ib + t) * 128 + col2];
                    const int ao = (ig + t) * 16 + (t < 2 ? oA : oB);
                    const float4 v4 = ld4(&vT7[ao]);
                    A0 = fma2(splat(v4.x), w2, A0);
                    A1 = fma2(splat(v4.y), w2, A1);
                    A2 = fma2(splat(v4.z), w2, A2);
                    A3 = fma2(splat(v4.w), w2, A3);
                }
            }
            if (ic == 1 && ks == 1) {
                float l0,h0,l1,h1,l2,h2,l3,h3;
                unpk2(A0,l0,h0); unpk2(A1,l1,h1); unpk2(A2,l2,h2); unpk2(A3,l3,h3);
                st4(&scr[col2 * 16 + rb_s],       make_float4(l0,l1,l2,l3));
                st4(&scr[(col2 + 1) * 16 + rb_s], make_float4(h0,h1,h2,h3));
            }
            if (lane == 0) mbar_arrive(mbarE + (uint32_t)(c & 1) * 8u);
            c++;
        }
        __syncthreads();
        if (ks == 0) {
            const float4 p0 = ld4(&scr[col2 * 16 + rb_s]);
            const float4 p1 = ld4(&scr[(col2 + 1) * 16 + rb_s]);
            const float b0 = DT_A * bb[7 * 128 + col2];
            const float b1 = DT_A * bb[7 * 128 + col2 + 1];
            float l0,h0,l1,h1,l2,h2,l3,h3;
            unpk2(A0,l0,h0); unpk2(A1,l1,h1); unpk2(A2,l2,h2); unpk2(A3,l3,h3);
            const float sl[4] = {l0+p0.x, l1+p0.y, l2+p0.z, l3+p0.w};
            const float sh[4] = {h0+p1.x, h1+p1.y, h2+p1.z, h3+p1.w};
#pragma unroll
            for (int i = 0; i < 4; i++) {
                const int r = rbase + i;
                const float r0 = zinT[col2 * 16 + rb_s + i]       + b0 - DT_A * sl[i];
                const float r1 = zinT[(col2 + 1) * 16 + rb_s + i] + b1 - DT_A * sh[i];
                *(ull*)&qT[r * 128 + col2] = pk2(r0, r1);
            }
        }
        __syncthreads();
    }

    // ---- logits + softmax ----
    for (int t = tid; t < 160; t += 512) {
        const int r = t / 10, o = t % 10;
        const float* ur = qT + r * 128;
        const float* wr = wout + o * 128;
        float a = bout[o];
#pragma unroll 4
        for (int k = 0; k < U; k++) a += ur[k] * wr[k];
        lg[t] = a;
    }
    __syncthreads();
    if (tid < 16) {
        float mx = -1e30f;
#pragma unroll
        for (int o = 0; o < 10; o++) mx = fmaxf(mx, lg[tid * 10 + o]);
        float e[10], s = 0.f;
#pragma unroll
        for (int o = 0; o < 10; o++) { e[o] = expf(lg[tid * 10 + o] - mx); s += e[o]; }
        const float inv = 1.0f / s;
#pragma unroll
        for (int o = 0; o < 10; o++) out[(row0 + tid) * 10 + o] = e[o] * inv;
    }
}

extern "C" void kernel_launch(void* const* d_in, const int* in_sizes, int n_in,
                              void* d_out, int out_size)
{
    const float* x     = (const float*)d_in[0];
    const float* w_in  = (const float*)d_in[1];
    const float* b_in  = (const float*)d_in[2];
    const float* w_blk = (const float*)d_in[3];
    const float* b_blk = (const float*)d_in[4];
    const float* w_out = (const float*)d_in[5];
    const float* b_out = (const float*)d_in[6];
    float* out = (float*)d_out;

    cudaFuncSetAttribute(k_pre,   cudaFuncAttributeMaxDynamicSharedMemorySize, PREP_SMEM);
    cudaFuncSetAttribute(k_sweep, cudaFuncAttributeMaxDynamicSharedMemorySize, SW_BYTES);

    k_pre  <<<144, 512, PREP_SMEM>>>(x, w_in, b_in, w_blk, b_blk);
    k_sweep<<<128, 512, SW_BYTES>>>(w_blk, b_blk, w_out, b_out, out);
}

// round 17
// speedup vs baseline: 2.7585x; 1.2489x over previous
#include <cuda_runtime.h>
#include <cstdint>
#include <math.h>

#define BATCH    2048
#define U        128
#define NLAYERS  8
#define NSTEPS   3            // measured: err increment ~10x/sweep; rel_err ~1.2e-5 at 3
#define DT_A     0.1f
#define INVC     (1.0f/11.0f)
#define TANHK    10.0f
#define NCHUNKS  (NSTEPS * NLAYERS * 6 + 2)   // 146

typedef unsigned long long ull;

__device__ float g_zin[BATCH * 256];
__device__ float g_Mt [NLAYERS * U * U];
__device__ float g_Nt [NLAYERS * U * U];      // pre-negated -(a/c) M W
__device__ float g_Mb [NLAYERS * U];
__device__ float g_WT [U * U];

__device__ __forceinline__ float4 ld4(const float* p) { return *(const float4*)p; }
__device__ __forceinline__ float2 ld2(const float* p) { return *(const float2*)p; }
__device__ __forceinline__ void   st4(float* p, float4 v) { *(float4*)p = v; }
#define FC(v,t) (((const float*)&(v))[t])

__device__ __forceinline__ ull pk2(float x, float y) {
    ull r; asm("mov.b64 %0, {%1,%2};" : "=l"(r) : "f"(x), "f"(y)); return r;
}
__device__ __forceinline__ ull splat(float x) { return pk2(x, x); }
__device__ __forceinline__ ull fma2(ull a, ull b, ull c) {
    ull d; asm("fma.rn.f32x2 %0, %1, %2, %3;" : "=l"(d) : "l"(a), "l"(b), "l"(c)); return d;
}
__device__ __forceinline__ void unpk2(ull v, float& lo, float& hi) {
    asm("mov.b64 {%0,%1}, %2;" : "=f"(lo), "=f"(hi) : "l"(v));
}
__device__ __forceinline__ uint32_t s2u(const void* p) {
    uint32_t a;
    asm("{ .reg .u64 t; cvta.to.shared.u64 t, %1; cvt.u32.u64 %0, t; }" : "=r"(a) : "l"(p));
    return a;
}
__device__ __forceinline__ void mbar_init(uint32_t m, uint32_t cnt) {
    asm volatile("mbarrier.init.shared.b64 [%0], %1;" :: "r"(m), "r"(cnt) : "memory");
}
__device__ __forceinline__ void mbar_expect(uint32_t m, uint32_t tx) {
    asm volatile("mbarrier.arrive.expect_tx.shared.b64 _, [%0], %1;" :: "r"(m), "r"(tx) : "memory");
}
__device__ __forceinline__ void mbar_arrive(uint32_t m) {
    asm volatile("mbarrier.arrive.release.cta.shared.b64 _, [%0];" :: "r"(m) : "memory");
}
__device__ __forceinline__ void bulk_g2s(uint32_t dst, const void* src, uint32_t bytes, uint32_t m) {
    asm volatile("cp.async.bulk.shared::cluster.global.mbarrier::complete_tx::bytes [%0], [%1], %2, [%3];"
                 :: "r"(dst), "l"(src), "r"(bytes), "r"(m) : "memory");
}
__device__ __forceinline__ void mbar_wait(uint32_t m, uint32_t phase) {
    uint32_t done;
    do {
        asm volatile("{\n\t.reg .pred p;\n\t"
                     "mbarrier.try_wait.parity.acquire.cta.shared::cta.b64 p, [%1], %2, 0x989680;\n\t"
                     "selp.b32 %0, 1, 0, p;\n\t}"
                     : "=r"(done) : "r"(m), "r"(phase) : "memory");
    } while (!done);
}
__device__ __forceinline__ int swz(int col) { return ((col >> 1) & 3) << 2; }

// ---------------- k_pre: prep halves (CTAs 0..15) + input proj (16..143), 512 thr ----
#define WS_S 132
#define ES   132
#define MS   68
#define PREP_SMEM ((128*WS_S + 128*ES + 128*MS) * 4)

__device__ void prep_body(float* sm, const float* __restrict__ wblocks,
                          const float* __restrict__ bblocks, int cid)
{
    float* Wsh = sm;                  // [128][132]
    float* E   = sm + 128 * WS_S;     // [128][132]
    float* Mh  = E + 128 * ES;        // [128][68]
    const int tid = threadIdx.x;
    const int l  = cid >> 1;
    const int h  = cid & 1;
    const int j0 = h * 64;
    const float* Wg = wblocks + l * U * U;

    for (int idx = tid; idx < U * U; idx += 512)
        Wsh[(idx >> 7) * WS_S + (idx & 127)] = Wg[idx];
    __syncthreads();

    // E = kscl * W W^T   (interleaved cols: tj + 16*j -> 2-way LDS conflicts)
    const float kscl = (DT_A * DT_A) * INVC;
    {
        const int ti = tid >> 4, tj = tid & 15;
        float acc[4][8];
#pragma unroll
        for (int r = 0; r < 4; r++)
#pragma unroll
            for (int j = 0; j < 8; j++) acc[r][j] = 0.f;
        for (int k4 = 0; k4 < 32; k4++) {
            float4 wi[4], wj[8];
#pragma unroll
            for (int r = 0; r < 4; r++) wi[r] = ld4(&Wsh[(ti*4 + r) * WS_S + k4*4]);
#pragma unroll
            for (int j = 0; j < 8; j++) wj[j] = ld4(&Wsh[(tj + 16*j) * WS_S + k4*4]);
#pragma unroll
            for (int r = 0; r < 4; r++)
#pragma unroll
                for (int j = 0; j < 8; j++) {
                    acc[r][j] += wi[r].x * wj[j].x + wi[r].y * wj[j].y
                               + wi[r].z * wj[j].z + wi[r].w * wj[j].w;
                }
        }
#pragma unroll
        for (int r = 0; r < 4; r++)
#pragma unroll
            for (int j = 0; j < 8; j++)
                E[(ti*4 + r) * ES + tj + 16*j] = kscl * acc[r][j];
    }
    __syncthreads();

    // M-half = I - E + E^2 (cols j0 + tj + 16*cjj; E symmetric -> row dots)
    {
        const int ti = tid >> 4, tj = tid & 15;
        float acc[4][4];
#pragma unroll
        for (int r = 0; r < 4; r++)
#pragma unroll
            for (int cjj = 0; cjj < 4; cjj++) acc[r][cjj] = 0.f;
        for (int k4 = 0; k4 < 32; k4++) {
            float4 ei[4], ej[4];
#pragma unroll
            for (int r = 0; r < 4; r++)   ei[r] = ld4(&E[(ti*4 + r) * ES + k4*4]);
#pragma unroll
            for (int cjj = 0; cjj < 4; cjj++) ej[cjj] = ld4(&E[(j0 + tj + 16*cjj) * ES + k4*4]);
#pragma unroll
            for (int r = 0; r < 4; r++)
#pragma unroll
                for (int cjj = 0; cjj < 4; cjj++) {
                    acc[r][cjj] += ei[r].x * ej[cjj].x + ei[r].y * ej[cjj].y
                                 + ei[r].z * ej[cjj].z + ei[r].w * ej[cjj].w;
                }
        }
#pragma unroll
        for (int r = 0; r < 4; r++)
#pragma unroll
            for (int cjj = 0; cjj < 4; cjj++) {
                const int i = ti*4 + r;
                const int jc = tj + 16*cjj;
                const int j = j0 + jc;
                Mh[i * MS + jc] =
                    (i == j ? 1.f : 0.f) - E[i * ES + j] + acc[r][cjj];
            }
    }
    __syncthreads();

    for (int idx = tid; idx < 128 * 64; idx += 512) {
        const int k = idx >> 6, jh = idx & 63;
        g_Mt[l * 16384 + k * 128 + j0 + jh] = Mh[k * MS + jh];
    }
    if (tid < 64) {
        float s = 0.f;
        for (int m = 0; m < U; m++)
            s += Mh[m * MS + tid] * bblocks[l * U + m];
        g_Mb[l * U + j0 + tid] = DT_A * s;
    }
    {
        const float ac = -DT_A * INVC;
        const int tk = tid >> 4, tj = tid & 15;
        float acc[4][4];
#pragma unroll
        for (int r = 0; r < 4; r++)
#pragma unroll
            for (int cjj = 0; cjj < 4; cjj++) acc[r][cjj] = 0.f;
#pragma unroll 2
        for (int m = 0; m < U; m++) {
            const float4 wv = ld4(&Wsh[m * WS_S + tk*4]);
            const float4 mv = ld4(&Mh[m * MS + tj*4]);
#pragma unroll
            for (int r = 0; r < 4; r++)
#pragma unroll
                for (int cjj = 0; cjj < 4; cjj++)
                    acc[r][cjj] += FC(wv, r) * FC(mv, cjj);
        }
#pragma unroll
        for (int r = 0; r < 4; r++)
#pragma unroll
            for (int cjj = 0; cjj < 4; cjj++)
                g_Nt[l * 16384 + (tk*4 + r) * 128 + j0 + tj*4 + cjj] = ac * acc[r][cjj];
    }
    if (l == NLAYERS - 1 && h == 0) {
        for (int idx = tid; idx < U * U; idx += 512) {
            const int i = idx >> 7, j = idx & 127;
            g_WT[i * U + j] = Wsh[j * WS_S + i];
        }
    }
}

__device__ void input_body(float* sm, const float* __restrict__ x,
                           const float* __restrict__ win,
                           const float* __restrict__ bin, int bid)
{
    float* ws = sm;            // [16][132]
    float* xs = sm + 16 * 132; // [16][20]
    const int tid = threadIdx.x;
    const int row0 = bid * 16;
    const int rg = tid >> 6;   // 0..7, 2 rows each
    const int cg = tid & 63;   // 2 cols each

    float2 acc[2];
    acc[0] = make_float2(0.f, 0.f);
    acc[1] = make_float2(0.f, 0.f);

    for (int kc = 0; kc < 49; kc++) {
        const int k0 = kc * 16;
        __syncthreads();
        {
            const int n = tid & 127, h = tid >> 7;
            const float* wr = win + n * 784 + k0 + h * 4;
            float4 a = ld4(wr);
            ws[(h*4+0)*132 + n] = a.x; ws[(h*4+1)*132 + n] = a.y;
            ws[(h*4+2)*132 + n] = a.z; ws[(h*4+3)*132 + n] = a.w;
        }
        if (tid < 256) {
            const int r = tid >> 4, kk = tid & 15;
            xs[kk * 20 + r] = x[(row0 + r) * 784 + k0 + kk];
        }
        __syncthreads();
#pragma unroll
        for (int kk = 0; kk < 16; kk++) {
            const float2 wv = ld2(&ws[kk * 132 + cg * 2]);
            const float xv0 = xs[kk * 20 + rg * 2];
            const float xv1 = xs[kk * 20 + rg * 2 + 1];
            acc[0].x += xv0 * wv.x; acc[0].y += xv0 * wv.y;
            acc[1].x += xv1 * wv.x; acc[1].y += xv1 * wv.y;
        }
    }

    const float2 b2 = ld2(bin + cg * 2);
    acc[0].x += b2.x; acc[0].y += b2.y;
    acc[1].x += b2.x; acc[1].y += b2.y;
    float* base = g_zin + bid * 4096;
#pragma unroll
    for (int cc = 0; cc < 2; cc++) {
        const int col = cg * 2 + cc;
        const int so = (rg * 2) ^ swz(col);
        const float a0 = cc ? acc[0].y : acc[0].x;
        const float a1 = cc ? acc[1].y : acc[1].x;
        *(ull*)&base[col * 16 + so]        = pk2(a0, a1);
        *(ull*)&base[2048 + col * 16 + so] = pk2(tanhf(a0), tanhf(a1));
    }
}

__global__ __launch_bounds__(512) void k_pre(const float* __restrict__ x,
                                             const float* __restrict__ win,
                                             const float* __restrict__ bin,
                                             const float* __restrict__ wblocks,
                                             const float* __restrict__ bblocks)
{
    extern __shared__ float sm[];
    if (blockIdx.x < 16) prep_body(sm, wblocks, bblocks, blockIdx.x);
    else                 input_body(sm, x, win, bin, blockIdx.x - 16);
}

// ---------------- k_sweep ----------------
#define SW_FLOATS 57512
#define SW_BYTES  (SW_FLOATS * 4)

__device__ __forceinline__ void prefetch_chunk(int c, uint32_t wbB, uint32_t mbar0,
                                               const float* __restrict__ wblocks)
{
    if (c >= NCHUNKS) return;
    const uint32_t dst = wbB + (uint32_t)(c & 1) * 32768u;
    const uint32_t mb  = mbar0 + (uint32_t)(c & 1) * 8u;
    mbar_expect(mb, 32768u);
    if (c >= NCHUNKS - 2) {
        bulk_g2s(dst, g_WT + (c - (NCHUNKS - 2)) * 8192, 32768u, mb);
    } else {
        const int step = c / 6;
        const int l = step & 7;
        const int r = c - step * 6;
        if (r < 4) {
            bulk_g2s(dst,          g_Mt + l * 16384 + r * 4096, 16384u, mb);
            bulk_g2s(dst + 16384u, g_Nt + l * 16384 + r * 4096, 16384u, mb);
        } else {
            bulk_g2s(dst, wblocks + l * 16384 + (r - 4) * 8192, 32768u, mb);
        }
    }
}

__global__ __launch_bounds__(512, 1) void k_sweep(const float* __restrict__ wblocks,
                                                  const float* __restrict__ bblocks,
                                                  const float* __restrict__ wout,
                                                  const float* __restrict__ bout,
                                                  float* __restrict__ out)
{
    extern __shared__ float sm[];
    float* zinT = sm;
    float* zls  = sm + 4096;
    float* qT   = sm + 36864;
    float* wb   = sm + 38912;
    float* bb   = sm + 55296;
    float* Mbs  = sm + 56320;
    float* lg   = sm + 57344;

    const uint32_t smem0 = s2u(sm);
    const uint32_t mbar0 = smem0 + 57504u * 4u;
    const uint32_t mbarE = smem0 + 57508u * 4u;
    const uint32_t wbB   = smem0 + 38912u * 4u;

    const int tid  = threadIdx.x;
    const int wid  = tid >> 5;
    const int lane = tid & 31;
    const int ks   = wid >> 3;
    const int rh   = (wid >> 2) & 1;
    const int cq   = wid & 3;
    const int rg   = lane >> 4;
    const int cp   = lane & 15;
    const int col2  = cq * 32 + cp * 2;
    const int rbase = rh * 8 + rg * 4;
    const int rb_s  = rbase ^ ((cp & 3) << 2);
    const int ks16  = ks * 16;
    const int row0  = blockIdx.x * 16;

    for (int idx = tid; idx < 4096; idx += 512) zinT[idx] = g_zin[row0 * 256 + idx];
    for (int idx = tid; idx < 1024; idx += 512) bb[idx] = bblocks[idx];
    for (int idx = tid; idx < 1024; idx += 512) Mbs[idx] = g_Mb[idx];
    if (tid == 0) {
        mbar_init(mbar0, 1);
        mbar_init(mbar0 + 8, 1);
        mbar_init(mbarE, 16);
        mbar_init(mbarE + 8, 16);
        asm volatile("fence.mbarrier_init.release.cluster;" ::: "memory");
    }
    __syncthreads();
    for (int idx = tid; idx < 32768; idx += 512) zls[idx] = zinT[idx & 4095];
#pragma unroll
    for (int s = 0; s < 2; s++) {
        const int ii = tid + s * 512;
        const int base = (ii >> 3) * 16 + (ii & 7) * 2;
        const float2 u2 = *(const float2*)&zinT[base];
        const float2 v2 = *(const float2*)&zinT[2048 + base];
        float2 q2;
        q2.x = TANHK * tanhf(u2.x) + v2.x;
        q2.y = TANHK * tanhf(u2.y) + v2.y;
        *(float2*)&qT[base] = q2;
    }
    if (tid == 0) { prefetch_chunk(0, wbB, mbar0, wblocks); prefetch_chunk(1, wbB, mbar0, wblocks); }
    __syncthreads();

    int c = 0;
    for (int it = 0; it < NSTEPS; it++) {
        for (int l = 0; l < NLAYERS; l++) {
            const float* cuT = l ? (zls + (l - 1) * 4096) : zinT;
            float* uTl = zls + l * 4096;
            float* vTl = uTl + 2048;

            // ---- u = M*carry + Mb + Ntneg*q (k-split; ring-synced) ----
            ull A0, A1, A2, A3;
            if (ks == 0) {
                const ull mb2 = *(const ull*)&Mbs[l * 128 + col2];
                A0 = mb2; A1 = mb2; A2 = mb2; A3 = mb2;
            } else {
                A0 = A1 = A2 = A3 = 0;
            }
            for (int kc = 0; kc < 4; kc++) {
                mbar_wait(mbar0 + (uint32_t)(c & 1) * 8u, (c >> 1) & 1);
                const float* Mt = wb + (c & 1) * 8192;
                const float* Nt = Mt + 4096;
#pragma unroll
                for (int kk4 = 0; kk4 < 4; kk4++) {
                    const int kb = ks16 + kk4 * 4;
                    const int kg = kc * 32 + kb;
                    const int oA = rbase ^ (((kg >> 1) & 3) << 2);
                    const int oB = rbase ^ ((((kg >> 1) + 1) & 3) << 2);
#pragma unroll
                    for (int t = 0; t < 4; t++) {
                        const ull mw = *(const ull*)&Mt[(kb + t) * 128 + col2];
                        const ull nw = *(const ull*)&Nt[(kb + t) * 128 + col2];
                        const int ao = (kg + t) * 16 + (t < 2 ? oA : oB);
                        const float4 cu = ld4(&cuT[ao]);
                        const float4 qq = ld4(&qT[ao]);
                        A0 = fma2(splat(cu.x), mw, A0);
                        A1 = fma2(splat(cu.y), mw, A1);
                        A2 = fma2(splat(cu.z), mw, A2);
                        A3 = fma2(splat(cu.w), mw, A3);
                        A0 = fma2(splat(qq.x), nw, A0);
                        A1 = fma2(splat(qq.y), nw, A1);
                        A2 = fma2(splat(qq.z), nw, A2);
                        A3 = fma2(splat(qq.w), nw, A3);
                    }
                }
                if (kc == 3 && ks == 1) {
                    float l0,h0,l1,h1,l2,h2,l3,h3;
                    unpk2(A0,l0,h0); unpk2(A1,l1,h1); unpk2(A2,l2,h2); unpk2(A3,l3,h3);
                    st4(&uTl[col2 * 16 + rb_s],       make_float4(l0,l1,l2,l3));
                    st4(&uTl[(col2 + 1) * 16 + rb_s], make_float4(h0,h1,h2,h3));
                }
                if (lane == 0) mbar_arrive(mbarE + (uint32_t)(c & 1) * 8u);
                if (wid == 0 && lane == 0 && c + 2 < NCHUNKS) {
                    mbar_wait(mbarE + (uint32_t)(c & 1) * 8u, (c >> 1) & 1);
                    prefetch_chunk(c + 2, wbB, mbar0, wblocks);
                }
                c++;
            }
            __syncthreads();
            if (ks == 0) {
                const float4 p0 = ld4(&uTl[col2 * 16 + rb_s]);
                const float4 p1 = ld4(&uTl[(col2 + 1) * 16 + rb_s]);
                float l0,h0,l1,h1,l2,h2,l3,h3;
                unpk2(A0,l0,h0); unpk2(A1,l1,h1); unpk2(A2,l2,h2); unpk2(A3,l3,h3);
                st4(&uTl[col2 * 16 + rb_s],
                    make_float4(l0+p0.x, l1+p0.y, l2+p0.z, l3+p0.w));
                st4(&uTl[(col2 + 1) * 16 + rb_s],
                    make_float4(h0+p1.x, h1+p1.y, h2+p1.z, h3+p1.w));
            }
            __syncthreads();

            // ---- v = (q + 0.1 * u W)/11 (j-split; ring-synced) ----
            ull V0 = 0, V1 = 0, V2 = 0, V3 = 0;
            for (int jc = 0; jc < 2; jc++) {
                mbar_wait(mbar0 + (uint32_t)(c & 1) * 8u, (c >> 1) & 1);
                const float* Ws = wb + (c & 1) * 8192;
#pragma unroll
                for (int jj4 = 0; jj4 < 8; jj4++) {
                    const int jb = ks * 32 + jj4 * 4;
                    const int jg = jc * 64 + jb;
                    const int oA = rbase ^ (((jg >> 1) & 3) << 2);
                    const int oB = rbase ^ ((((jg >> 1) + 1) & 3) << 2);
#pragma unroll
                    for (int t = 0; t < 4; t++) {
                        const ull w2 = *(const ull*)&Ws[(jb + t) * 128 + col2];
                        const int ao = (jg + t) * 16 + (t < 2 ? oA : oB);
                        const float4 u4 = ld4(&uTl[ao]);
                        V0 = fma2(splat(u4.x), w2, V0);
                        V1 = fma2(splat(u4.y), w2, V1);
                        V2 = fma2(splat(u4.z), w2, V2);
                        V3 = fma2(splat(u4.w), w2, V3);
                    }
                }
                if (jc == 1 && ks == 1) {
                    float l0,h0,l1,h1,l2,h2,l3,h3;
                    unpk2(V0,l0,h0); unpk2(V1,l1,h1); unpk2(V2,l2,h2); unpk2(V3,l3,h3);
                    st4(&vTl[col2 * 16 + rb_s],       make_float4(l0,l1,l2,l3));
                    st4(&vTl[(col2 + 1) * 16 + rb_s], make_float4(h0,h1,h2,h3));
                }
                if (lane == 0) mbar_arrive(mbarE + (uint32_t)(c & 1) * 8u);
                if (wid == 0 && lane == 0 && c + 2 < NCHUNKS) {
                    mbar_wait(mbarE + (uint32_t)(c & 1) * 8u, (c >> 1) & 1);
                    prefetch_chunk(c + 2, wbB, mbar0, wblocks);
                }
                c++;
            }
            __syncthreads();
            if (ks == 0) {
                const float4 p0 = ld4(&vTl[col2 * 16 + rb_s]);
                const float4 p1 = ld4(&vTl[(col2 + 1) * 16 + rb_s]);
                const float4 q0 = ld4(&qT[col2 * 16 + rb_s]);
                const float4 q1 = ld4(&qT[(col2 + 1) * 16 + rb_s]);
                float l0,h0,l1,h1,l2,h2,l3,h3;
                unpk2(V0,l0,h0); unpk2(V1,l1,h1); unpk2(V2,l2,h2); unpk2(V3,l3,h3);
                const float4 vv0 = make_float4(
                    (q0.x + DT_A * (l0 + p0.x)) * INVC,
                    (q0.y + DT_A * (l1 + p0.y)) * INVC,
                    (q0.z + DT_A * (l2 + p0.z)) * INVC,
                    (q0.w + DT_A * (l3 + p0.w)) * INVC);
                const float4 vv1 = make_float4(
                    (q1.x + DT_A * (h0 + p1.x)) * INVC,
                    (q1.y + DT_A * (h1 + p1.y)) * INVC,
                    (q1.z + DT_A * (h2 + p1.z)) * INVC,
                    (q1.w + DT_A * (h3 + p1.w)) * INVC);
                st4(&vTl[col2 * 16 + rb_s],       vv0);
                st4(&vTl[(col2 + 1) * 16 + rb_s], vv1);

                if (!(it == NSTEPS - 1 && l == NLAYERS - 1)) {
                    const float* uN = (l < NLAYERS - 1) ? (zls + (l + 1) * 4096) : zls;
                    const float4 un0 = ld4(&uN[col2 * 16 + rb_s]);
                    const float4 un1 = ld4(&uN[(col2 + 1) * 16 + rb_s]);
                    float4 cv0, cv1;
                    if (l < NLAYERS - 1) { cv0 = vv0; cv1 = vv1; }
                    else {
                        cv0 = ld4(&zinT[2048 + col2 * 16 + rb_s]);
                        cv1 = ld4(&zinT[2048 + (col2 + 1) * 16 + rb_s]);
                    }
                    float4 nq0, nq1;
                    nq0.x = TANHK * tanhf(un0.x) + cv0.x;
                    nq0.y = TANHK * tanhf(un0.y) + cv0.y;
                    nq0.z = TANHK * tanhf(un0.z) + cv0.z;
                    nq0.w = TANHK * tanhf(un0.w) + cv0.w;
                    nq1.x = TANHK * tanhf(un1.x) + cv1.x;
                    nq1.y = TANHK * tanhf(un1.y) + cv1.y;
                    nq1.z = TANHK * tanhf(un1.z) + cv1.z;
                    nq1.w = TANHK * tanhf(un1.w) + cv1.w;
                    st4(&qT[col2 * 16 + rb_s],       nq0);
                    st4(&qT[(col2 + 1) * 16 + rb_s], nq1);
                }
            }
            __syncthreads();
        }
    }

    // ---- final block -> qT row-major ----
    {
        ull A0 = 0, A1 = 0, A2 = 0, A3 = 0;
        const float* vT7 = zls + 7 * 4096 + 2048;
        float* scr = zls;
        for (int ic = 0; ic < 2; ic++) {
            mbar_wait(mbar0 + (uint32_t)(c & 1) * 8u, (c >> 1) & 1);
            const float* Ws = wb + (c & 1) * 8192;
#pragma unroll
            for (int ii4 = 0; ii4 < 8; ii4++) {
                const int ib = ks * 32 + ii4 * 4;
                const int ig = ic * 64 + ib;
                const int oA = rbase ^ (((ig >> 1) & 3) << 2);
                const int oB = rbase ^ ((((ig >> 1) + 1) & 3) << 2);
#pragma unroll
                for (int t = 0; t < 4; t++) {
                    const ull w2 = *(const ull*)&Ws[(ib + t) * 128 + col2];
                    const int ao = (ig + t) * 16 + (t < 2 ? oA : oB);
                    const float4 v4 = ld4(&vT7[ao]);
                    A0 = fma2(splat(v4.x), w2, A0);
                    A1 = fma2(splat(v4.y), w2, A1);
                    A2 = fma2(splat(v4.z), w2, A2);
                    A3 = fma2(splat(v4.w), w2, A3);
                }
            }
            if (ic == 1 && ks == 1) {
                float l0,h0,l1,h1,l2,h2,l3,h3;
                unpk2(A0,l0,h0); unpk2(A1,l1,h1); unpk2(A2,l2,h2); unpk2(A3,l3,h3);
                st4(&scr[col2 * 16 + rb_s],       make_float4(l0,l1,l2,l3));
                st4(&scr[(col2 + 1) * 16 + rb_s], make_float4(h0,h1,h2,h3));
            }
            if (lane == 0) mbar_arrive(mbarE + (uint32_t)(c & 1) * 8u);
            c++;
        }
        __syncthreads();
        if (ks == 0) {
            const float4 p0 = ld4(&scr[col2 * 16 + rb_s]);
            const float4 p1 = ld4(&scr[(col2 + 1) * 16 + rb_s]);
            const float b0 = DT_A * bb[7 * 128 + col2];
            const float b1 = DT_A * bb[7 * 128 + col2 + 1];
            float l0,h0,l1,h1,l2,h2,l3,h3;
            unpk2(A0,l0,h0); unpk2(A1,l1,h1); unpk2(A2,l2,h2); unpk2(A3,l3,h3);
            const float sl[4] = {l0+p0.x, l1+p0.y, l2+p0.z, l3+p0.w};
            const float sh[4] = {h0+p1.x, h1+p1.y, h2+p1.z, h3+p1.w};
#pragma unroll
            for (int i = 0; i < 4; i++) {
                const int r = rbase + i;
                const float r0 = zinT[col2 * 16 + rb_s + i]       + b0 - DT_A * sl[i];
                const float r1 = zinT[(col2 + 1) * 16 + rb_s + i] + b1 - DT_A * sh[i];
                *(ull*)&qT[r * 128 + col2] = pk2(r0, r1);
            }
        }
        __syncthreads();
    }

    // ---- logits + softmax ----
    for (int t = tid; t < 160; t += 512) {
        const int r = t / 10, o = t % 10;
        const float* ur = qT + r * 128;
        const float* wr = wout + o * 128;
        float a = bout[o];
#pragma unroll 4
        for (int k = 0; k < U; k++) a += ur[k] * wr[k];
        lg[t] = a;
    }
    __syncthreads();
    if (tid < 16) {
        float mx = -1e30f;
#pragma unroll
        for (int o = 0; o < 10; o++) mx = fmaxf(mx, lg[tid * 10 + o]);
        float e[10], s = 0.f;
#pragma unroll
        for (int o = 0; o < 10; o++) { e[o] = expf(lg[tid * 10 + o] - mx); s += e[o]; }
        const float inv = 1.0f / s;
#pragma unroll
        for (int o = 0; o < 10; o++) out[(row0 + tid) * 10 + o] = e[o] * inv;
    }
}

extern "C" void kernel_launch(void* const* d_in, const int* in_sizes, int n_in,
                              void* d_out, int out_size)
{
    const float* x     = (const float*)d_in[0];
    const float* w_in  = (const float*)d_in[1];
    const float* b_in  = (const float*)d_in[2];
    const float* w_blk = (const float*)d_in[3];
    const float* b_blk = (const float*)d_in[4];
    const float* w_out = (const float*)d_in[5];
    const float* b_out = (const float*)d_in[6];
    float* out = (float*)d_out;

    cudaFuncSetAttribute(k_pre,   cudaFuncAttributeMaxDynamicSharedMemorySize, PREP_SMEM);
    cudaFuncSetAttribute(k_sweep, cudaFuncAttributeMaxDynamicSharedMemorySize, SW_BYTES);

    k_pre  <<<144, 512, PREP_SMEM>>>(x, w_in, b_in, w_blk, b_blk);
    k_sweep<<<128, 512, SW_BYTES>>>(w_blk, b_blk, w_out, b_out, out);
}